// round 13
// baseline (speedup 1.0000x reference)
#include <cuda_runtime.h>
#include <cuda_fp16.h>
#include <cstdint>
#include <cstddef>

// ---------------------------------------------------------------------------
// GPT-2 transformer block. mma.sync + ldmatrix + cp.async. fp32 I/O.
// R13 = R9 + f16-accumulate GEMM chains (promote to fp32 once per BK=64 tile).
// ---------------------------------------------------------------------------

#define BATCH  4
#define SEQ    2048
#define DMODEL 1024
#define NHEAD  16
#define HDIM   64
#define DFF    4096
#define ROWS   (BATCH * SEQ)

// -------------------------- scratch (device globals) ----------------------
__device__ __half g_x16    [(size_t)ROWS * DMODEL];
__device__ __half g_wattnT [(size_t)3 * DMODEL * DMODEL];
__device__ __half g_waprojT[(size_t)DMODEL * DMODEL];
__device__ __half g_wfcT   [(size_t)DFF * DMODEL];
__device__ __half g_wmprojT[(size_t)DMODEL * DFF];
__device__ __half g_q16    [(size_t)ROWS * DMODEL];
__device__ __half g_k16    [(size_t)ROWS * DMODEL];
__device__ __half g_v16    [(size_t)ROWS * DMODEL];
__device__ __half g_a16    [(size_t)ROWS * DMODEL];
__device__ float  g_ap32   [(size_t)ROWS * DMODEL];
__device__ float  g_n32    [(size_t)ROWS * DMODEL];
__device__ __half g_n16    [(size_t)ROWS * DMODEL];
__device__ __half g_h16    [(size_t)ROWS * DFF];
__device__ float  g_m32    [(size_t)ROWS * DMODEL];

// ------------------------------ helpers -----------------------------------
__device__ __forceinline__ void mma16816(float c[4], const uint32_t a[4],
                                         const uint32_t b[2]) {
    asm volatile(
        "mma.sync.aligned.m16n8k16.row.col.f32.f16.f16.f32 "
        "{%0,%1,%2,%3}, {%4,%5,%6,%7}, {%8,%9}, {%0,%1,%2,%3};\n"
        : "+f"(c[0]), "+f"(c[1]), "+f"(c[2]), "+f"(c[3])
        : "r"(a[0]), "r"(a[1]), "r"(a[2]), "r"(a[3]), "r"(b[0]), "r"(b[1]));
}

// f16-accumulate variant: c = {half2(row g), half2(row g+8)}
__device__ __forceinline__ void mma16816h(uint32_t c[2], const uint32_t a[4],
                                          const uint32_t b[2]) {
    asm volatile(
        "mma.sync.aligned.m16n8k16.row.col.f16.f16.f16.f16 "
        "{%0,%1}, {%2,%3,%4,%5}, {%6,%7}, {%0,%1};\n"
        : "+r"(c[0]), "+r"(c[1])
        : "r"(a[0]), "r"(a[1]), "r"(a[2]), "r"(a[3]), "r"(b[0]), "r"(b[1]));
}

__device__ __forceinline__ void ldsm_x4(uint32_t r[4], uint32_t addr) {
    asm volatile("ldmatrix.sync.aligned.m8n8.x4.shared.b16 {%0,%1,%2,%3}, [%4];"
                 : "=r"(r[0]), "=r"(r[1]), "=r"(r[2]), "=r"(r[3]) : "r"(addr));
}

__device__ __forceinline__ void ldsm_x4_trans(uint32_t r[4], uint32_t addr) {
    asm volatile("ldmatrix.sync.aligned.m8n8.x4.trans.shared.b16 {%0,%1,%2,%3}, [%4];"
                 : "=r"(r[0]), "=r"(r[1]), "=r"(r[2]), "=r"(r[3]) : "r"(addr));
}

__device__ __forceinline__ void cp_async16(uint32_t smem, const void* gptr) {
    asm volatile("cp.async.cg.shared.global [%0], [%1], 16;\n" ::"r"(smem), "l"(gptr));
}
#define CP_COMMIT() asm volatile("cp.async.commit_group;\n" ::)
#define CP_WAIT(n)  asm volatile("cp.async.wait_group %0;\n" ::"n"(n))

__device__ __forceinline__ uint32_t smem_u32(const void* p) {
    uint32_t a;
    asm("{ .reg .u64 t; cvta.to.shared.u64 t, %1; cvt.u32.u64 %0, t; }"
        : "=r"(a) : "l"(p));
    return a;
}

__device__ __forceinline__ uint32_t pack_half2f(float a, float b) {
    __half2 h = __floats2half2_rn(a, b);
    return *reinterpret_cast<uint32_t*>(&h);
}

__device__ __forceinline__ float fast_exp2(float x) {
    float r;
    asm("ex2.approx.f32 %0, %1;" : "=f"(r) : "f"(x));
    return r;
}

__device__ __forceinline__ float gelu_f(float x) {
    const float k0 = 0.7978845608028654f;
    float u = k0 * (x + 0.044715f * x * x * x);
    float t;
    asm("tanh.approx.f32 %0, %1;" : "=f"(t) : "f"(u));
    return 0.5f * x * (1.0f + t);
}

// -------------------- fused prep: cvt + 4 weight transposes ----------------
__global__ __launch_bounds__(256) void prep_all(
    const float* __restrict__ x, const float* __restrict__ w_attn,
    const float* __restrict__ w_aproj, const float* __restrict__ w_fc,
    const float* __restrict__ w_mproj,
    __half* __restrict__ x16, __half* __restrict__ wattnT,
    __half* __restrict__ waprojT, __half* __restrict__ wfcT,
    __half* __restrict__ wmprojT) {
    int blk = blockIdx.x;
    const int tid = threadIdx.x;
    if (blk < 8192) {
        size_t off = (size_t)blk * DMODEL;
        float4 v = reinterpret_cast<const float4*>(x + off)[tid];
        __half2 h0 = __floats2half2_rn(v.x, v.y);
        __half2 h1 = __floats2half2_rn(v.z, v.w);
        *reinterpret_cast<uint2*>(x16 + off + tid * 4) =
            make_uint2(*reinterpret_cast<uint32_t*>(&h0),
                       *reinterpret_cast<uint32_t*>(&h1));
        return;
    }
    blk -= 8192;
    const float* src;
    __half* dst;
    int R, C;
    if (blk < 3072)      { src = w_attn;  dst = wattnT;  R = 1024; C = 3072; }
    else if (blk < 4096) { blk -= 3072; src = w_aproj; dst = waprojT; R = 1024; C = 1024; }
    else if (blk < 8192) { blk -= 4096; src = w_fc;    dst = wfcT;    R = 1024; C = 4096; }
    else                 { blk -= 8192; src = w_mproj; dst = wmprojT; R = 4096; C = 1024; }
    const int tilesX = C / 32;
    const int tx = blk % tilesX, ty = blk / tilesX;
    __shared__ float t[32][33];
    const int lx = tid & 31, ly = tid >> 5;
    const int c = tx * 32 + lx, r = ty * 32 + ly;
#pragma unroll
    for (int i = 0; i < 32; i += 8)
        t[ly + i][lx] = src[(size_t)(r + i) * C + c];
    __syncthreads();
    const int ox = tid & 15, oyb = tid >> 4;
#pragma unroll
    for (int i = 0; i < 32; i += 16) {
        int rr = oyb + i;
        uint32_t h = pack_half2f(t[2 * ox][rr], t[2 * ox + 1][rr]);
        *reinterpret_cast<uint32_t*>(
            &dst[(size_t)(tx * 32 + rr) * R + ty * 32 + 2 * ox]) = h;
    }
}

// ------------------------------- GEMM v8 -----------------------------------
// C[M,N] = A[M,K](f16 rm) * Bt[N,K](f16) + bias. CTA 128x64, 256 threads
// (4m x 2n warps, warp tile 32x32), BK=64, 2 stages. f16-accumulate within
// each BK=64 tile (4 chained MMAs), promoted to fp32 per tile. 2 CTAs/SM.
#define G6_BK   64
#define G6_LKB  144                    // 64 halves + pad (stride/16 = 9, odd)
#define G6_AST  (128 * G6_LKB)         // 18432 B
#define G6_BST  (64 * G6_LKB)          // 9216 B
#define G6_STG  (G6_AST + G6_BST)      // 27648 B
#define G6_SMEM (2 * G6_STG)           // 55296 B

enum { EPI_QKV = 0, EPI_F32 = 1, EPI_GELU = 2 };

template <int EPI>
__global__ __launch_bounds__(256, 2) void gemm_v8(
    const __half* __restrict__ A, const __half* __restrict__ Bt,
    const float* __restrict__ bias,
    float* __restrict__ outF, __half* __restrict__ outH,
    __half* __restrict__ oq, __half* __restrict__ ok, __half* __restrict__ ov,
    int N, int K) {
    extern __shared__ __align__(128) char smem[];
    const uint32_t sb = smem_u32(smem);

    const int tid  = threadIdx.x;
    const int warp = tid >> 5, lane = tid & 31;
    const int g = lane >> 2, tg = lane & 3;
    const int wm = warp >> 1, wn = warp & 1;
    const int bm = blockIdx.y * 128, bn = blockIdx.x * 64;
    const int KT = K / G6_BK;

    float acc[2][4][4];
#pragma unroll
    for (int i = 0; i < 2; i++)
#pragma unroll
        for (int j = 0; j < 4; j++)
#pragma unroll
            for (int q = 0; q < 4; q++) acc[i][j][q] = 0.f;

    const uint32_t a_lm = (uint32_t)((wm * 32 + (lane & 15)) * G6_LKB +
                                     (lane >> 4) * 16);
    const uint32_t b_lm = (uint32_t)(G6_AST +
        (wn * 32 + (lane & 7) + ((lane >> 4) << 3)) * G6_LKB +
        ((lane >> 3) & 1) * 16);

    auto load_tile = [&](int kt, int s) {
        const int k0 = kt * G6_BK;
        const uint32_t base = sb + s * G6_STG;
        // A: 128 rows x 128B = 1024 16B chunks (4 passes)
#pragma unroll
        for (int i = 0; i < 4; i++) {
            int idx = tid + i * 256;
            int row = idx >> 3, c = idx & 7;
            cp_async16(base + row * G6_LKB + c * 16,
                       &A[(size_t)(bm + row) * K + k0 + c * 8]);
        }
        // B: 64 rows x 128B = 512 chunks (2 passes)
#pragma unroll
        for (int i = 0; i < 2; i++) {
            int idx = tid + i * 256;
            int row = idx >> 3, c = idx & 7;
            cp_async16(base + G6_AST + row * G6_LKB + c * 16,
                       &Bt[(size_t)(bn + row) * K + k0 + c * 8]);
        }
        CP_COMMIT();
    };

    load_tile(0, 0);

    for (int t = 0; t < KT; t++) {
        CP_WAIT(0);
        __syncthreads();
        if (t + 1 < KT) load_tile(t + 1, (t + 1) & 1);

        const uint32_t stg = sb + (t & 1) * G6_STG;

        // f16 accumulators for this BK=64 tile
        uint32_t hacc[2][4][2];
#pragma unroll
        for (int mi = 0; mi < 2; mi++)
#pragma unroll
            for (int ni = 0; ni < 4; ni++) {
                hacc[mi][ni][0] = 0u;
                hacc[mi][ni][1] = 0u;
            }

#pragma unroll
        for (int kk = 0; kk < 4; kk++) {
            uint32_t a0[4], a1[4], b[4][2];
            ldsm_x4(a0, stg + a_lm + kk * 32);
            ldsm_x4(a1, stg + a_lm + 16 * G6_LKB + kk * 32);
#pragma unroll
            for (int p = 0; p < 2; p++) {
                uint32_t r[4];
                ldsm_x4(r, stg + b_lm + p * 16 * G6_LKB + kk * 32);
                b[p * 2][0] = r[0]; b[p * 2][1] = r[1];
                b[p * 2 + 1][0] = r[2]; b[p * 2 + 1][1] = r[3];
            }
#pragma unroll
            for (int ni = 0; ni < 4; ni++) {
                mma16816h(hacc[0][ni], a0, b[ni]);
                mma16816h(hacc[1][ni], a1, b[ni]);
            }
        }

        // promote tile partials to fp32
#pragma unroll
        for (int mi = 0; mi < 2; mi++)
#pragma unroll
            for (int ni = 0; ni < 4; ni++) {
                float2 f0 = __half22float2(
                    *reinterpret_cast<__half2*>(&hacc[mi][ni][0]));
                float2 f1 = __half22float2(
                    *reinterpret_cast<__half2*>(&hacc[mi][ni][1]));
                acc[mi][ni][0] += f0.x;
                acc[mi][ni][1] += f0.y;
                acc[mi][ni][2] += f1.x;
                acc[mi][ni][3] += f1.y;
            }
    }

    // ------------------------------ epilogue -------------------------------
#pragma unroll
    for (int mi = 0; mi < 2; mi++) {
        int r0 = bm + wm * 32 + mi * 16 + g;
        int r1 = r0 + 8;
#pragma unroll
        for (int ni = 0; ni < 4; ni++) {
            int c0 = bn + wn * 32 + ni * 8 + tg * 2;
            float bv0 = __ldg(&bias[c0]), bv1 = __ldg(&bias[c0 + 1]);
            float v00 = acc[mi][ni][0] + bv0, v01 = acc[mi][ni][1] + bv1;
            float v10 = acc[mi][ni][2] + bv0, v11 = acc[mi][ni][3] + bv1;
            if (EPI == EPI_F32) {
                *reinterpret_cast<float2*>(&outF[(size_t)r0 * N + c0]) =
                    make_float2(v00, v01);
                *reinterpret_cast<float2*>(&outF[(size_t)r1 * N + c0]) =
                    make_float2(v10, v11);
            } else if (EPI == EPI_GELU) {
                *reinterpret_cast<uint32_t*>(&outH[(size_t)r0 * N + c0]) =
                    pack_half2f(gelu_f(v00), gelu_f(v01));
                *reinterpret_cast<uint32_t*>(&outH[(size_t)r1 * N + c0]) =
                    pack_half2f(gelu_f(v10), gelu_f(v11));
            } else {  // EPI_QKV: scatter into per-head [B*H][S][hd]
                int which = c0 >> 10;
                int cc = c0 & 1023;
                int h = cc >> 6, d0 = cc & 63;
                __half* dst = which == 0 ? oq : which == 1 ? ok : ov;
                int b0i = r0 >> 11, s0i = r0 & 2047;
                int b1i = r1 >> 11, s1i = r1 & 2047;
                size_t i0 = ((size_t)(b0i * NHEAD + h) * SEQ + s0i) * HDIM + d0;
                size_t i1 = ((size_t)(b1i * NHEAD + h) * SEQ + s1i) * HDIM + d0;
                *reinterpret_cast<uint32_t*>(&dst[i0]) = pack_half2f(v00, v01);
                *reinterpret_cast<uint32_t*>(&dst[i1]) = pack_half2f(v10, v11);
            }
        }
    }
}

// --------------------------- flash attention v3 ----------------------------
// grid (S/128, B*H), 256 threads (8 warps x 16 q rows). Causal. K,V row-major,
// fragments via ldmatrix (V .trans), 3-stage cp.async, 1 sync per K-block.
#define AT_LKB 144
#define AT_KS  (128 * AT_LKB)         // 18432 B
#define AT_STG (2 * AT_KS)            // 36864 B (K + V)
#define ASMEM  (3 * AT_STG)           // 110592 B

__global__ __launch_bounds__(256, 1) void attn_kernel(
    const __half* __restrict__ Q, const __half* __restrict__ K,
    const __half* __restrict__ V, __half* __restrict__ Aout) {
    extern __shared__ __align__(128) char smem[];
    const uint32_t sb = smem_u32(smem);

    const int tid  = threadIdx.x;
    const int warp = tid >> 5, lane = tid & 31;
    const int g = lane >> 2, tg = lane & 3;
    const int bh = blockIdx.y;
    const int qb = blockIdx.x;
    const size_t base = (size_t)bh * SEQ * HDIM;

    auto load_kv = [&](int kb, int s) {
        const uint32_t bs = sb + s * AT_STG;
#pragma unroll
        for (int i = 0; i < 4; i++) {
            int idx = tid + i * 256;
            int row = idx >> 3, c = idx & 7;
            cp_async16(bs + row * AT_LKB + c * 16,
                       &K[base + (size_t)(kb * 128 + row) * HDIM + c * 8]);
        }
#pragma unroll
        for (int i = 0; i < 4; i++) {
            int idx = tid + i * 256;
            int row = idx >> 3, c = idx & 7;
            cp_async16(bs + AT_KS + row * AT_LKB + c * 16,
                       &V[base + (size_t)(kb * 128 + row) * HDIM + c * 8]);
        }
        CP_COMMIT();
    };

    load_kv(0, 0);

    // stage Q into stage-2 K area (its frags are lifted immediately)
#pragma unroll
    for (int i = 0; i < 4; i++) {
        int idx = tid + i * 256;
        int row = idx >> 3, c = idx & 7;
        *reinterpret_cast<uint4*>(smem + 2 * AT_STG + row * AT_LKB + c * 16) =
            *reinterpret_cast<const uint4*>(
                &Q[base + (size_t)(qb * 128 + row) * HDIM + c * 8]);
    }
    __syncthreads();
    uint32_t qa[4][4];
    {
        const uint32_t q_lm = sb + 2 * AT_STG +
            (warp * 16 + (lane & 15)) * AT_LKB + (lane >> 4) * 16;
#pragma unroll
        for (int kt = 0; kt < 4; kt++) ldsm_x4(qa[kt], q_lm + kt * 32);
    }

    const uint32_t k_lm = (uint32_t)(((lane & 7) + ((lane >> 4) << 3)) * AT_LKB +
                                     ((lane >> 3) & 1) * 16);
    const uint32_t v_lm = (uint32_t)(((lane & 7) + (((lane >> 3) & 1) << 3)) * AT_LKB +
                                     (lane >> 4) * 16);

    float o[8][4];
#pragma unroll
    for (int i = 0; i < 8; i++)
#pragma unroll
        for (int j = 0; j < 4; j++) o[i][j] = 0.f;
    float m0 = -1e30f, m1 = -1e30f, l0 = 0.f, l1 = 0.f;
    const int q0 = qb * 128 + warp * 16 + g;
    const int q1 = q0 + 8;

    int stage = 0;
    for (int kblk = 0; kblk <= qb; kblk++) {
        if (kblk < qb) {
            int s1 = stage + 1;
            if (s1 >= 3) s1 -= 3;
            load_kv(kblk + 1, s1);
        } else {
            CP_COMMIT();
        }
        CP_WAIT(1);
        __syncthreads();
        const uint32_t ks = sb + stage * AT_STG;
        const uint32_t vs = ks + AT_KS;

        float sacc[16][4];
#pragma unroll
        for (int nt = 0; nt < 16; nt++)
#pragma unroll
            for (int j = 0; j < 4; j++) sacc[nt][j] = 0.f;
#pragma unroll
        for (int kt = 0; kt < 4; kt++) {
#pragma unroll
            for (int pair = 0; pair < 8; pair++) {
                uint32_t r[4];
                ldsm_x4(r, ks + k_lm + pair * 16 * AT_LKB + kt * 32);
                mma16816(sacc[pair * 2],     qa[kt], r);
                mma16816(sacc[pair * 2 + 1], qa[kt], r + 2);
            }
        }

        const float scale = 0.18033688011112042f;  // rsqrt(64)*log2(e)
        const int kbase = kblk * 128;
#pragma unroll
        for (int nt = 0; nt < 16; nt++) {
            int c0 = kbase + nt * 8 + tg * 2;
            sacc[nt][0] *= scale; sacc[nt][1] *= scale;
            sacc[nt][2] *= scale; sacc[nt][3] *= scale;
            if (kblk == qb) {
                if (c0 > q0)     sacc[nt][0] = -1e30f;
                if (c0 + 1 > q0) sacc[nt][1] = -1e30f;
                if (c0 > q1)     sacc[nt][2] = -1e30f;
                if (c0 + 1 > q1) sacc[nt][3] = -1e30f;
            }
        }

        float nm0 = m0, nm1 = m1;
#pragma unroll
        for (int nt = 0; nt < 16; nt++) {
            nm0 = fmaxf(nm0, fmaxf(sacc[nt][0], sacc[nt][1]));
            nm1 = fmaxf(nm1, fmaxf(sacc[nt][2], sacc[nt][3]));
        }
        nm0 = fmaxf(nm0, __shfl_xor_sync(0xffffffffu, nm0, 1));
        nm0 = fmaxf(nm0, __shfl_xor_sync(0xffffffffu, nm0, 2));
        nm1 = fmaxf(nm1, __shfl_xor_sync(0xffffffffu, nm1, 1));
        nm1 = fmaxf(nm1, __shfl_xor_sync(0xffffffffu, nm1, 2));
        float alpha0 = fast_exp2(m0 - nm0), alpha1 = fast_exp2(m1 - nm1);

        float ls0 = 0.f, ls1 = 0.f;
        uint32_t pa[8][4];
#pragma unroll
        for (int nt = 0; nt < 16; nt++) {
            __half2 e0 = h2exp2(__floats2half2_rn(sacc[nt][0] - nm0,
                                                  sacc[nt][1] - nm0));
            __half2 e1 = h2exp2(__floats2half2_rn(sacc[nt][2] - nm1,
                                                  sacc[nt][3] - nm1));
            float2 f0 = __half22float2(e0);
            float2 f1 = __half22float2(e1);
            ls0 += f0.x + f0.y;
            ls1 += f1.x + f1.y;
            int kt = nt >> 1, hi = nt & 1;
            pa[kt][hi * 2 + 0] = *reinterpret_cast<uint32_t*>(&e0);
            pa[kt][hi * 2 + 1] = *reinterpret_cast<uint32_t*>(&e1);
        }
        ls0 += __shfl_xor_sync(0xffffffffu, ls0, 1);
        ls0 += __shfl_xor_sync(0xffffffffu, ls0, 2);
        ls1 += __shfl_xor_sync(0xffffffffu, ls1, 1);
        ls1 += __shfl_xor_sync(0xffffffffu, ls1, 2);
        l0 = l0 * alpha0 + ls0;
        l1 = l1 * alpha1 + ls1;
        m0 = nm0;
        m1 = nm1;
#pragma unroll
        for (int dnt = 0; dnt < 8; dnt++) {
            o[dnt][0] *= alpha0; o[dnt][1] *= alpha0;
            o[dnt][2] *= alpha1; o[dnt][3] *= alpha1;
        }

#pragma unroll
        for (int kt = 0; kt < 8; kt++) {
#pragma unroll
            for (int dp = 0; dp < 4; dp++) {
                uint32_t r[4];
                ldsm_x4_trans(r, vs + v_lm + kt * 16 * AT_LKB + dp * 32);
                mma16816(o[dp * 2],     pa[kt], r);
                mma16816(o[dp * 2 + 1], pa[kt], r + 2);
            }
        }
        stage = (stage == 2) ? 0 : stage + 1;
    }

    float inv0 = 1.f / l0, inv1 = 1.f / l1;
    int b = bh >> 4, h = bh & 15;
    int s0 = qb * 128 + warp * 16 + g;
    size_t r0 = (size_t)(b * SEQ + s0) * DMODEL + h * HDIM;
    size_t r1 = r0 + (size_t)8 * DMODEL;
#pragma unroll
    for (int dnt = 0; dnt < 8; dnt++) {
        int d = dnt * 8 + tg * 2;
        *reinterpret_cast<uint32_t*>(&Aout[r0 + d]) =
            pack_half2f(o[dnt][0] * inv0, o[dnt][1] * inv0);
        *reinterpret_cast<uint32_t*>(&Aout[r1 + d]) =
            pack_half2f(o[dnt][2] * inv1, o[dnt][3] * inv1);
    }
}

// --------------------------- residual + layernorm --------------------------
__global__ __launch_bounds__(256) void ln_kernel(
    const float* __restrict__ X, const float* __restrict__ Y,
    const float* __restrict__ gg, const float* __restrict__ bb,
    float* __restrict__ out32, __half* __restrict__ out16) {
    const int row = blockIdx.x, tid = threadIdx.x;
    const float* x = X + (size_t)row * DMODEL;
    const float* y = Y + (size_t)row * DMODEL;
    float v[4];
    float s = 0.f;
#pragma unroll
    for (int i = 0; i < 4; i++) {
        int c = tid + i * 256;
        v[i] = x[c] + y[c];
        s += v[i];
    }
    __shared__ float red[8], red2[8];
#pragma unroll
    for (int o = 16; o; o >>= 1) s += __shfl_xor_sync(0xffffffffu, s, o);
    if ((tid & 31) == 0) red[tid >> 5] = s;
    __syncthreads();
    float tot = 0.f;
#pragma unroll
    for (int i = 0; i < 8; i++) tot += red[i];
    float mean = tot * (1.0f / DMODEL);

    float s2 = 0.f;
#pragma unroll
    for (int i = 0; i < 4; i++) {
        float d = v[i] - mean;
        s2 += d * d;
    }
#pragma unroll
    for (int o = 16; o; o >>= 1) s2 += __shfl_xor_sync(0xffffffffu, s2, o);
    if ((tid & 31) == 0) red2[tid >> 5] = s2;
    __syncthreads();
    float tot2 = 0.f;
#pragma unroll
    for (int i = 0; i < 8; i++) tot2 += red2[i];
    float rstd = rsqrtf(tot2 * (1.0f / DMODEL) + 1e-5f);

#pragma unroll
    for (int i = 0; i < 4; i++) {
        int c = tid + i * 256;
        float nv = (v[i] - mean) * rstd * gg[c] + bb[c];
        out32[(size_t)row * DMODEL + c] = nv;
        if (out16) out16[(size_t)row * DMODEL + c] = __float2half(nv);
    }
}

// ------------------------------- host --------------------------------------
extern "C" void kernel_launch(void* const* d_in, const int* in_sizes, int n_in,
                              void* d_out, int out_size) {
    const float* x       = (const float*)d_in[0];
    const float* w_attn  = (const float*)d_in[1];
    const float* b_attn  = (const float*)d_in[2];
    const float* w_aproj = (const float*)d_in[3];
    const float* b_aproj = (const float*)d_in[4];
    const float* g1      = (const float*)d_in[5];
    const float* b1      = (const float*)d_in[6];
    const float* w_fc    = (const float*)d_in[7];
    const float* b_fc    = (const float*)d_in[8];
    const float* w_mproj = (const float*)d_in[9];
    const float* b_mproj = (const float*)d_in[10];
    const float* g2      = (const float*)d_in[11];
    const float* b2      = (const float*)d_in[12];
    float* out = (float*)d_out;

    __half *x16, *wattnT, *waprojT, *wfcT, *wmprojT, *q16, *k16, *v16, *a16, *n16, *h16;
    float *ap32, *n32, *m32;
    cudaGetSymbolAddress((void**)&x16,     g_x16);
    cudaGetSymbolAddress((void**)&wattnT,  g_wattnT);
    cudaGetSymbolAddress((void**)&waprojT, g_waprojT);
    cudaGetSymbolAddress((void**)&wfcT,    g_wfcT);
    cudaGetSymbolAddress((void**)&wmprojT, g_wmprojT);
    cudaGetSymbolAddress((void**)&q16,     g_q16);
    cudaGetSymbolAddress((void**)&k16,     g_k16);
    cudaGetSymbolAddress((void**)&v16,     g_v16);
    cudaGetSymbolAddress((void**)&a16,     g_a16);
    cudaGetSymbolAddress((void**)&n16,     g_n16);
    cudaGetSymbolAddress((void**)&h16,     g_h16);
    cudaGetSymbolAddress((void**)&ap32,    g_ap32);
    cudaGetSymbolAddress((void**)&n32,     g_n32);
    cudaGetSymbolAddress((void**)&m32,     g_m32);

    cudaFuncSetAttribute(gemm_v8<EPI_QKV>,  cudaFuncAttributeMaxDynamicSharedMemorySize, G6_SMEM);
    cudaFuncSetAttribute(gemm_v8<EPI_F32>,  cudaFuncAttributeMaxDynamicSharedMemorySize, G6_SMEM);
    cudaFuncSetAttribute(gemm_v8<EPI_GELU>, cudaFuncAttributeMaxDynamicSharedMemorySize, G6_SMEM);
    cudaFuncSetAttribute(attn_kernel,       cudaFuncAttributeMaxDynamicSharedMemorySize, ASMEM);

    // launch 0: fused prep
    prep_all<<<20480, 256>>>(x, w_attn, w_aproj, w_fc, w_mproj,
                             x16, wattnT, waprojT, wfcT, wmprojT);

    // launch 1: qkv (N = 3072, K = 1024)
    gemm_v8<EPI_QKV><<<dim3(3 * DMODEL / 64, ROWS / 128), 256, G6_SMEM>>>(
        x16, wattnT, b_attn, nullptr, nullptr, q16, k16, v16, 3 * DMODEL, DMODEL);

    // launch 2: attention
    attn_kernel<<<dim3(SEQ / 128, BATCH * NHEAD), 256, ASMEM>>>(q16, k16, v16, a16);

    // launch 3: aproj (N = K = 1024)
    gemm_v8<EPI_F32><<<dim3(DMODEL / 64, ROWS / 128), 256, G6_SMEM>>>(
        a16, waprojT, b_aproj, ap32, nullptr, nullptr, nullptr, nullptr,
        DMODEL, DMODEL);

    // launch 4: n = LN(x + aproj)
    ln_kernel<<<ROWS, 256>>>(x, ap32, g1, b1, n32, n16);

    // launch 5: fc + gelu (N = 4096, K = 1024)   <- ncu -s 5 -c 1 captures this
    gemm_v8<EPI_GELU><<<dim3(DFF / 64, ROWS / 128), 256, G6_SMEM>>>(
        n16, wfcT, b_fc, nullptr, h16, nullptr, nullptr, nullptr,
        DFF, DMODEL);

    // launch 6: mproj (N = 1024, K = 4096)
    gemm_v8<EPI_F32><<<dim3(DMODEL / 64, ROWS / 128), 256, G6_SMEM>>>(
        h16, wmprojT, b_mproj, m32, nullptr, nullptr, nullptr, nullptr,
        DMODEL, DFF);

    // launch 7: out = LN(n + m)
    ln_kernel<<<ROWS, 256>>>(n32, m32, g2, b2, out, nullptr);
}

// round 14
// speedup vs baseline: 1.1352x; 1.1352x over previous
#include <cuda_runtime.h>
#include <cuda_fp16.h>
#include <cstdint>
#include <cstddef>

// ---------------------------------------------------------------------------
// GPT-2 transformer block. mma.sync + ldmatrix + cp.async. fp32 I/O, fp16
// compute, fp32 acc. R14 = R9 (best 866us) + vectorized LN/prep side kernels.
// ---------------------------------------------------------------------------

#define BATCH  4
#define SEQ    2048
#define DMODEL 1024
#define NHEAD  16
#define HDIM   64
#define DFF    4096
#define ROWS   (BATCH * SEQ)

// -------------------------- scratch (device globals) ----------------------
__device__ __half g_x16    [(size_t)ROWS * DMODEL];
__device__ __half g_wattnT [(size_t)3 * DMODEL * DMODEL];
__device__ __half g_waprojT[(size_t)DMODEL * DMODEL];
__device__ __half g_wfcT   [(size_t)DFF * DMODEL];
__device__ __half g_wmprojT[(size_t)DMODEL * DFF];
__device__ __half g_q16    [(size_t)ROWS * DMODEL];
__device__ __half g_k16    [(size_t)ROWS * DMODEL];
__device__ __half g_v16    [(size_t)ROWS * DMODEL];
__device__ __half g_a16    [(size_t)ROWS * DMODEL];
__device__ float  g_ap32   [(size_t)ROWS * DMODEL];
__device__ float  g_n32    [(size_t)ROWS * DMODEL];
__device__ __half g_n16    [(size_t)ROWS * DMODEL];
__device__ __half g_h16    [(size_t)ROWS * DFF];
__device__ float  g_m32    [(size_t)ROWS * DMODEL];

// ------------------------------ helpers -----------------------------------
__device__ __forceinline__ void mma16816(float c[4], const uint32_t a[4],
                                         const uint32_t b[2]) {
    asm volatile(
        "mma.sync.aligned.m16n8k16.row.col.f32.f16.f16.f32 "
        "{%0,%1,%2,%3}, {%4,%5,%6,%7}, {%8,%9}, {%0,%1,%2,%3};\n"
        : "+f"(c[0]), "+f"(c[1]), "+f"(c[2]), "+f"(c[3])
        : "r"(a[0]), "r"(a[1]), "r"(a[2]), "r"(a[3]), "r"(b[0]), "r"(b[1]));
}

__device__ __forceinline__ void ldsm_x4(uint32_t r[4], uint32_t addr) {
    asm volatile("ldmatrix.sync.aligned.m8n8.x4.shared.b16 {%0,%1,%2,%3}, [%4];"
                 : "=r"(r[0]), "=r"(r[1]), "=r"(r[2]), "=r"(r[3]) : "r"(addr));
}

__device__ __forceinline__ void ldsm_x4_trans(uint32_t r[4], uint32_t addr) {
    asm volatile("ldmatrix.sync.aligned.m8n8.x4.trans.shared.b16 {%0,%1,%2,%3}, [%4];"
                 : "=r"(r[0]), "=r"(r[1]), "=r"(r[2]), "=r"(r[3]) : "r"(addr));
}

__device__ __forceinline__ void cp_async16(uint32_t smem, const void* gptr) {
    asm volatile("cp.async.cg.shared.global [%0], [%1], 16;\n" ::"r"(smem), "l"(gptr));
}
#define CP_COMMIT() asm volatile("cp.async.commit_group;\n" ::)
#define CP_WAIT(n)  asm volatile("cp.async.wait_group %0;\n" ::"n"(n))

__device__ __forceinline__ uint32_t smem_u32(const void* p) {
    uint32_t a;
    asm("{ .reg .u64 t; cvta.to.shared.u64 t, %1; cvt.u32.u64 %0, t; }"
        : "=r"(a) : "l"(p));
    return a;
}

__device__ __forceinline__ uint32_t pack_half2f(float a, float b) {
    __half2 h = __floats2half2_rn(a, b);
    return *reinterpret_cast<uint32_t*>(&h);
}

__device__ __forceinline__ float fast_exp2(float x) {
    float r;
    asm("ex2.approx.f32 %0, %1;" : "=f"(r) : "f"(x));
    return r;
}

__device__ __forceinline__ float gelu_f(float x) {
    const float k0 = 0.7978845608028654f;
    float u = k0 * (x + 0.044715f * x * x * x);
    float t;
    asm("tanh.approx.f32 %0, %1;" : "=f"(t) : "f"(u));
    return 0.5f * x * (1.0f + t);
}

// -------------------- fused prep: cvt + 4 weight transposes ----------------
// blocks [0,8192): x rows -> fp16 (float4 path). blocks >= 8192: 32x32
// transpose tiles; the whole tile is staged with ONE float4 load per thread.
__global__ __launch_bounds__(256) void prep_all(
    const float* __restrict__ x, const float* __restrict__ w_attn,
    const float* __restrict__ w_aproj, const float* __restrict__ w_fc,
    const float* __restrict__ w_mproj,
    __half* __restrict__ x16, __half* __restrict__ wattnT,
    __half* __restrict__ waprojT, __half* __restrict__ wfcT,
    __half* __restrict__ wmprojT) {
    int blk = blockIdx.x;
    const int tid = threadIdx.x;
    if (blk < 8192) {
        size_t off = (size_t)blk * DMODEL;
        float4 v = reinterpret_cast<const float4*>(x + off)[tid];
        __half2 h0 = __floats2half2_rn(v.x, v.y);
        __half2 h1 = __floats2half2_rn(v.z, v.w);
        *reinterpret_cast<uint2*>(x16 + off + tid * 4) =
            make_uint2(*reinterpret_cast<uint32_t*>(&h0),
                       *reinterpret_cast<uint32_t*>(&h1));
        return;
    }
    blk -= 8192;
    const float* src;
    __half* dst;
    int R, C;
    if (blk < 3072)      { src = w_attn;  dst = wattnT;  R = 1024; C = 3072; }
    else if (blk < 4096) { blk -= 3072; src = w_aproj; dst = waprojT; R = 1024; C = 1024; }
    else if (blk < 8192) { blk -= 4096; src = w_fc;    dst = wfcT;    R = 1024; C = 4096; }
    else                 { blk -= 8192; src = w_mproj; dst = wmprojT; R = 4096; C = 1024; }
    const int tilesX = C / 32;
    const int tx = blk % tilesX, ty = blk / tilesX;
    __shared__ float t[32][33];
    // stage tile: one float4 load per thread (row = tid>>3, 4 cols)
    {
        const int row = tid >> 3, c4 = (tid & 7) * 4;
        float4 v = *reinterpret_cast<const float4*>(
            &src[(size_t)(ty * 32 + row) * C + tx * 32 + c4]);
        t[row][c4 + 0] = v.x;
        t[row][c4 + 1] = v.y;
        t[row][c4 + 2] = v.z;
        t[row][c4 + 3] = v.w;
    }
    __syncthreads();
    const int ox = tid & 15, oyb = tid >> 4;
#pragma unroll
    for (int i = 0; i < 32; i += 16) {
        int rr = oyb + i;
        uint32_t h = pack_half2f(t[2 * ox][rr], t[2 * ox + 1][rr]);
        *reinterpret_cast<uint32_t*>(
            &dst[(size_t)(tx * 32 + rr) * R + ty * 32 + 2 * ox]) = h;
    }
}

// ------------------------------- GEMM v6 -----------------------------------
// C[M,N] = A[M,K](f16 rm) * Bt[N,K](f16) + bias. CTA 128x64, 256 threads
// (4m x 2n warps, warp tile 32x32), BK=64, 2 stages, 3 CTAs/SM (24 warps).
#define G6_BK   64
#define G6_LKB  144                    // 64 halves + pad (stride/16 = 9, odd)
#define G6_AST  (128 * G6_LKB)         // 18432 B
#define G6_BST  (64 * G6_LKB)          // 9216 B
#define G6_STG  (G6_AST + G6_BST)      // 27648 B
#define G6_SMEM (2 * G6_STG)           // 55296 B

enum { EPI_QKV = 0, EPI_F32 = 1, EPI_GELU = 2 };

template <int EPI>
__global__ __launch_bounds__(256, 3) void gemm_v6(
    const __half* __restrict__ A, const __half* __restrict__ Bt,
    const float* __restrict__ bias,
    float* __restrict__ outF, __half* __restrict__ outH,
    __half* __restrict__ oq, __half* __restrict__ ok, __half* __restrict__ ov,
    int N, int K) {
    extern __shared__ __align__(128) char smem[];
    const uint32_t sb = smem_u32(smem);

    const int tid  = threadIdx.x;
    const int warp = tid >> 5, lane = tid & 31;
    const int g = lane >> 2, tg = lane & 3;
    const int wm = warp >> 1, wn = warp & 1;
    const int bm = blockIdx.y * 128, bn = blockIdx.x * 64;
    const int KT = K / G6_BK;

    float acc[2][4][4];
#pragma unroll
    for (int i = 0; i < 2; i++)
#pragma unroll
        for (int j = 0; j < 4; j++)
#pragma unroll
            for (int q = 0; q < 4; q++) acc[i][j][q] = 0.f;

    const uint32_t a_lm = (uint32_t)((wm * 32 + (lane & 15)) * G6_LKB +
                                     (lane >> 4) * 16);
    const uint32_t b_lm = (uint32_t)(G6_AST +
        (wn * 32 + (lane & 7) + ((lane >> 4) << 3)) * G6_LKB +
        ((lane >> 3) & 1) * 16);

    auto load_tile = [&](int kt, int s) {
        const int k0 = kt * G6_BK;
        const uint32_t base = sb + s * G6_STG;
        // A: 128 rows x 128B = 1024 16B chunks (4 passes)
#pragma unroll
        for (int i = 0; i < 4; i++) {
            int idx = tid + i * 256;
            int row = idx >> 3, c = idx & 7;
            cp_async16(base + row * G6_LKB + c * 16,
                       &A[(size_t)(bm + row) * K + k0 + c * 8]);
        }
        // B: 64 rows x 128B = 512 chunks (2 passes)
#pragma unroll
        for (int i = 0; i < 2; i++) {
            int idx = tid + i * 256;
            int row = idx >> 3, c = idx & 7;
            cp_async16(base + G6_AST + row * G6_LKB + c * 16,
                       &Bt[(size_t)(bn + row) * K + k0 + c * 8]);
        }
        CP_COMMIT();
    };

    load_tile(0, 0);

    for (int t = 0; t < KT; t++) {
        CP_WAIT(0);
        __syncthreads();
        if (t + 1 < KT) load_tile(t + 1, (t + 1) & 1);

        const uint32_t stg = sb + (t & 1) * G6_STG;
#pragma unroll
        for (int kk = 0; kk < 4; kk++) {
            uint32_t a0[4], a1[4], b[4][2];
            ldsm_x4(a0, stg + a_lm + kk * 32);
            ldsm_x4(a1, stg + a_lm + 16 * G6_LKB + kk * 32);
#pragma unroll
            for (int p = 0; p < 2; p++) {
                uint32_t r[4];
                ldsm_x4(r, stg + b_lm + p * 16 * G6_LKB + kk * 32);
                b[p * 2][0] = r[0]; b[p * 2][1] = r[1];
                b[p * 2 + 1][0] = r[2]; b[p * 2 + 1][1] = r[3];
            }
#pragma unroll
            for (int ni = 0; ni < 4; ni++) {
                mma16816(acc[0][ni], a0, b[ni]);
                mma16816(acc[1][ni], a1, b[ni]);
            }
        }
    }

    // ------------------------------ epilogue -------------------------------
#pragma unroll
    for (int mi = 0; mi < 2; mi++) {
        int r0 = bm + wm * 32 + mi * 16 + g;
        int r1 = r0 + 8;
#pragma unroll
        for (int ni = 0; ni < 4; ni++) {
            int c0 = bn + wn * 32 + ni * 8 + tg * 2;
            float bv0 = __ldg(&bias[c0]), bv1 = __ldg(&bias[c0 + 1]);
            float v00 = acc[mi][ni][0] + bv0, v01 = acc[mi][ni][1] + bv1;
            float v10 = acc[mi][ni][2] + bv0, v11 = acc[mi][ni][3] + bv1;
            if (EPI == EPI_F32) {
                *reinterpret_cast<float2*>(&outF[(size_t)r0 * N + c0]) =
                    make_float2(v00, v01);
                *reinterpret_cast<float2*>(&outF[(size_t)r1 * N + c0]) =
                    make_float2(v10, v11);
            } else if (EPI == EPI_GELU) {
                *reinterpret_cast<uint32_t*>(&outH[(size_t)r0 * N + c0]) =
                    pack_half2f(gelu_f(v00), gelu_f(v01));
                *reinterpret_cast<uint32_t*>(&outH[(size_t)r1 * N + c0]) =
                    pack_half2f(gelu_f(v10), gelu_f(v11));
            } else {  // EPI_QKV: scatter into per-head [B*H][S][hd]
                int which = c0 >> 10;
                int cc = c0 & 1023;
                int h = cc >> 6, d0 = cc & 63;
                __half* dst = which == 0 ? oq : which == 1 ? ok : ov;
                int b0i = r0 >> 11, s0i = r0 & 2047;
                int b1i = r1 >> 11, s1i = r1 & 2047;
                size_t i0 = ((size_t)(b0i * NHEAD + h) * SEQ + s0i) * HDIM + d0;
                size_t i1 = ((size_t)(b1i * NHEAD + h) * SEQ + s1i) * HDIM + d0;
                *reinterpret_cast<uint32_t*>(&dst[i0]) = pack_half2f(v00, v01);
                *reinterpret_cast<uint32_t*>(&dst[i1]) = pack_half2f(v10, v11);
            }
        }
    }
}

// --------------------------- flash attention v3 ----------------------------
// grid (S/128, B*H), 256 threads (8 warps x 16 q rows). Causal. K,V row-major,
// fragments via ldmatrix (V .trans), 3-stage cp.async, 1 sync per K-block.
#define AT_LKB 144
#define AT_KS  (128 * AT_LKB)         // 18432 B
#define AT_STG (2 * AT_KS)            // 36864 B (K + V)
#define ASMEM  (3 * AT_STG)           // 110592 B

__global__ __launch_bounds__(256, 1) void attn_kernel(
    const __half* __restrict__ Q, const __half* __restrict__ K,
    const __half* __restrict__ V, __half* __restrict__ Aout) {
    extern __shared__ __align__(128) char smem[];
    const uint32_t sb = smem_u32(smem);

    const int tid  = threadIdx.x;
    const int warp = tid >> 5, lane = tid & 31;
    const int g = lane >> 2, tg = lane & 3;
    const int bh = blockIdx.y;
    const int qb = blockIdx.x;
    const size_t base = (size_t)bh * SEQ * HDIM;

    auto load_kv = [&](int kb, int s) {
        const uint32_t bs = sb + s * AT_STG;
#pragma unroll
        for (int i = 0; i < 4; i++) {
            int idx = tid + i * 256;
            int row = idx >> 3, c = idx & 7;
            cp_async16(bs + row * AT_LKB + c * 16,
                       &K[base + (size_t)(kb * 128 + row) * HDIM + c * 8]);
        }
#pragma unroll
        for (int i = 0; i < 4; i++) {
            int idx = tid + i * 256;
            int row = idx >> 3, c = idx & 7;
            cp_async16(bs + AT_KS + row * AT_LKB + c * 16,
                       &V[base + (size_t)(kb * 128 + row) * HDIM + c * 8]);
        }
        CP_COMMIT();
    };

    load_kv(0, 0);

    // stage Q into stage-2 K area (its frags are lifted immediately)
#pragma unroll
    for (int i = 0; i < 4; i++) {
        int idx = tid + i * 256;
        int row = idx >> 3, c = idx & 7;
        *reinterpret_cast<uint4*>(smem + 2 * AT_STG + row * AT_LKB + c * 16) =
            *reinterpret_cast<const uint4*>(
                &Q[base + (size_t)(qb * 128 + row) * HDIM + c * 8]);
    }
    __syncthreads();
    uint32_t qa[4][4];
    {
        const uint32_t q_lm = sb + 2 * AT_STG +
            (warp * 16 + (lane & 15)) * AT_LKB + (lane >> 4) * 16;
#pragma unroll
        for (int kt = 0; kt < 4; kt++) ldsm_x4(qa[kt], q_lm + kt * 32);
    }

    const uint32_t k_lm = (uint32_t)(((lane & 7) + ((lane >> 4) << 3)) * AT_LKB +
                                     ((lane >> 3) & 1) * 16);
    const uint32_t v_lm = (uint32_t)(((lane & 7) + (((lane >> 3) & 1) << 3)) * AT_LKB +
                                     (lane >> 4) * 16);

    float o[8][4];
#pragma unroll
    for (int i = 0; i < 8; i++)
#pragma unroll
        for (int j = 0; j < 4; j++) o[i][j] = 0.f;
    float m0 = -1e30f, m1 = -1e30f, l0 = 0.f, l1 = 0.f;
    const int q0 = qb * 128 + warp * 16 + g;
    const int q1 = q0 + 8;

    int stage = 0;
    for (int kblk = 0; kblk <= qb; kblk++) {
        if (kblk < qb) {
            int s1 = stage + 1;
            if (s1 >= 3) s1 -= 3;
            load_kv(kblk + 1, s1);
        } else {
            CP_COMMIT();
        }
        CP_WAIT(1);
        __syncthreads();
        const uint32_t ks = sb + stage * AT_STG;
        const uint32_t vs = ks + AT_KS;

        float sacc[16][4];
#pragma unroll
        for (int nt = 0; nt < 16; nt++)
#pragma unroll
            for (int j = 0; j < 4; j++) sacc[nt][j] = 0.f;
#pragma unroll
        for (int kt = 0; kt < 4; kt++) {
#pragma unroll
            for (int pair = 0; pair < 8; pair++) {
                uint32_t r[4];
                ldsm_x4(r, ks + k_lm + pair * 16 * AT_LKB + kt * 32);
                mma16816(sacc[pair * 2],     qa[kt], r);
                mma16816(sacc[pair * 2 + 1], qa[kt], r + 2);
            }
        }

        const float scale = 0.18033688011112042f;  // rsqrt(64)*log2(e)
        const int kbase = kblk * 128;
#pragma unroll
        for (int nt = 0; nt < 16; nt++) {
            int c0 = kbase + nt * 8 + tg * 2;
            sacc[nt][0] *= scale; sacc[nt][1] *= scale;
            sacc[nt][2] *= scale; sacc[nt][3] *= scale;
            if (kblk == qb) {
                if (c0 > q0)     sacc[nt][0] = -1e30f;
                if (c0 + 1 > q0) sacc[nt][1] = -1e30f;
                if (c0 > q1)     sacc[nt][2] = -1e30f;
                if (c0 + 1 > q1) sacc[nt][3] = -1e30f;
            }
        }

        float nm0 = m0, nm1 = m1;
#pragma unroll
        for (int nt = 0; nt < 16; nt++) {
            nm0 = fmaxf(nm0, fmaxf(sacc[nt][0], sacc[nt][1]));
            nm1 = fmaxf(nm1, fmaxf(sacc[nt][2], sacc[nt][3]));
        }
        nm0 = fmaxf(nm0, __shfl_xor_sync(0xffffffffu, nm0, 1));
        nm0 = fmaxf(nm0, __shfl_xor_sync(0xffffffffu, nm0, 2));
        nm1 = fmaxf(nm1, __shfl_xor_sync(0xffffffffu, nm1, 1));
        nm1 = fmaxf(nm1, __shfl_xor_sync(0xffffffffu, nm1, 2));
        float alpha0 = fast_exp2(m0 - nm0), alpha1 = fast_exp2(m1 - nm1);

        float ls0 = 0.f, ls1 = 0.f;
        uint32_t pa[8][4];
#pragma unroll
        for (int nt = 0; nt < 16; nt++) {
            __half2 e0 = h2exp2(__floats2half2_rn(sacc[nt][0] - nm0,
                                                  sacc[nt][1] - nm0));
            __half2 e1 = h2exp2(__floats2half2_rn(sacc[nt][2] - nm1,
                                                  sacc[nt][3] - nm1));
            float2 f0 = __half22float2(e0);
            float2 f1 = __half22float2(e1);
            ls0 += f0.x + f0.y;
            ls1 += f1.x + f1.y;
            int kt = nt >> 1, hi = nt & 1;
            pa[kt][hi * 2 + 0] = *reinterpret_cast<uint32_t*>(&e0);
            pa[kt][hi * 2 + 1] = *reinterpret_cast<uint32_t*>(&e1);
        }
        ls0 += __shfl_xor_sync(0xffffffffu, ls0, 1);
        ls0 += __shfl_xor_sync(0xffffffffu, ls0, 2);
        ls1 += __shfl_xor_sync(0xffffffffu, ls1, 1);
        ls1 += __shfl_xor_sync(0xffffffffu, ls1, 2);
        l0 = l0 * alpha0 + ls0;
        l1 = l1 * alpha1 + ls1;
        m0 = nm0;
        m1 = nm1;
#pragma unroll
        for (int dnt = 0; dnt < 8; dnt++) {
            o[dnt][0] *= alpha0; o[dnt][1] *= alpha0;
            o[dnt][2] *= alpha1; o[dnt][3] *= alpha1;
        }

#pragma unroll
        for (int kt = 0; kt < 8; kt++) {
#pragma unroll
            for (int dp = 0; dp < 4; dp++) {
                uint32_t r[4];
                ldsm_x4_trans(r, vs + v_lm + kt * 16 * AT_LKB + dp * 32);
                mma16816(o[dp * 2],     pa[kt], r);
                mma16816(o[dp * 2 + 1], pa[kt], r + 2);
            }
        }
        stage = (stage == 2) ? 0 : stage + 1;
    }

    float inv0 = 1.f / l0, inv1 = 1.f / l1;
    int b = bh >> 4, h = bh & 15;
    int s0 = qb * 128 + warp * 16 + g;
    size_t r0 = (size_t)(b * SEQ + s0) * DMODEL + h * HDIM;
    size_t r1 = r0 + (size_t)8 * DMODEL;
#pragma unroll
    for (int dnt = 0; dnt < 8; dnt++) {
        int d = dnt * 8 + tg * 2;
        *reinterpret_cast<uint32_t*>(&Aout[r0 + d]) =
            pack_half2f(o[dnt][0] * inv0, o[dnt][1] * inv0);
        *reinterpret_cast<uint32_t*>(&Aout[r1 + d]) =
            pack_half2f(o[dnt][2] * inv1, o[dnt][3] * inv1);
    }
}

// --------------------------- residual + layernorm --------------------------
// out = LN(X + Y) * g + b; optional fp16 copy. One block per row; each
// thread owns 4 contiguous columns (single float4 per operand).
__global__ __launch_bounds__(256) void ln_kernel(
    const float* __restrict__ X, const float* __restrict__ Y,
    const float* __restrict__ gg, const float* __restrict__ bb,
    float* __restrict__ out32, __half* __restrict__ out16) {
    const int row = blockIdx.x, tid = threadIdx.x;
    const size_t roff = (size_t)row * DMODEL;
    float4 xv = reinterpret_cast<const float4*>(X + roff)[tid];
    float4 yv = reinterpret_cast<const float4*>(Y + roff)[tid];
    float v[4] = {xv.x + yv.x, xv.y + yv.y, xv.z + yv.z, xv.w + yv.w};
    float s = v[0] + v[1] + v[2] + v[3];

    __shared__ float red[8], red2[8];
#pragma unroll
    for (int o = 16; o; o >>= 1) s += __shfl_xor_sync(0xffffffffu, s, o);
    if ((tid & 31) == 0) red[tid >> 5] = s;
    __syncthreads();
    float tot = 0.f;
#pragma unroll
    for (int i = 0; i < 8; i++) tot += red[i];
    float mean = tot * (1.0f / DMODEL);

    float s2 = 0.f;
#pragma unroll
    for (int i = 0; i < 4; i++) {
        float d = v[i] - mean;
        s2 += d * d;
    }
#pragma unroll
    for (int o = 16; o; o >>= 1) s2 += __shfl_xor_sync(0xffffffffu, s2, o);
    if ((tid & 31) == 0) red2[tid >> 5] = s2;
    __syncthreads();
    float tot2 = 0.f;
#pragma unroll
    for (int i = 0; i < 8; i++) tot2 += red2[i];
    float rstd = rsqrtf(tot2 * (1.0f / DMODEL) + 1e-5f);

    float4 gv = reinterpret_cast<const float4*>(gg)[tid];
    float4 bv = reinterpret_cast<const float4*>(bb)[tid];
    float4 nv;
    nv.x = (v[0] - mean) * rstd * gv.x + bv.x;
    nv.y = (v[1] - mean) * rstd * gv.y + bv.y;
    nv.z = (v[2] - mean) * rstd * gv.z + bv.z;
    nv.w = (v[3] - mean) * rstd * gv.w + bv.w;
    reinterpret_cast<float4*>(out32 + roff)[tid] = nv;
    if (out16) {
        *reinterpret_cast<uint2*>(out16 + roff + tid * 4) =
            make_uint2(pack_half2f(nv.x, nv.y), pack_half2f(nv.z, nv.w));
    }
}

// ------------------------------- host --------------------------------------
extern "C" void kernel_launch(void* const* d_in, const int* in_sizes, int n_in,
                              void* d_out, int out_size) {
    const float* x       = (const float*)d_in[0];
    const float* w_attn  = (const float*)d_in[1];
    const float* b_attn  = (const float*)d_in[2];
    const float* w_aproj = (const float*)d_in[3];
    const float* b_aproj = (const float*)d_in[4];
    const float* g1      = (const float*)d_in[5];
    const float* b1      = (const float*)d_in[6];
    const float* w_fc    = (const float*)d_in[7];
    const float* b_fc    = (const float*)d_in[8];
    const float* w_mproj = (const float*)d_in[9];
    const float* b_mproj = (const float*)d_in[10];
    const float* g2      = (const float*)d_in[11];
    const float* b2      = (const float*)d_in[12];
    float* out = (float*)d_out;

    __half *x16, *wattnT, *waprojT, *wfcT, *wmprojT, *q16, *k16, *v16, *a16, *n16, *h16;
    float *ap32, *n32, *m32;
    cudaGetSymbolAddress((void**)&x16,     g_x16);
    cudaGetSymbolAddress((void**)&wattnT,  g_wattnT);
    cudaGetSymbolAddress((void**)&waprojT, g_waprojT);
    cudaGetSymbolAddress((void**)&wfcT,    g_wfcT);
    cudaGetSymbolAddress((void**)&wmprojT, g_wmprojT);
    cudaGetSymbolAddress((void**)&q16,     g_q16);
    cudaGetSymbolAddress((void**)&k16,     g_k16);
    cudaGetSymbolAddress((void**)&v16,     g_v16);
    cudaGetSymbolAddress((void**)&a16,     g_a16);
    cudaGetSymbolAddress((void**)&n16,     g_n16);
    cudaGetSymbolAddress((void**)&h16,     g_h16);
    cudaGetSymbolAddress((void**)&ap32,    g_ap32);
    cudaGetSymbolAddress((void**)&n32,     g_n32);
    cudaGetSymbolAddress((void**)&m32,     g_m32);

    cudaFuncSetAttribute(gemm_v6<EPI_QKV>,  cudaFuncAttributeMaxDynamicSharedMemorySize, G6_SMEM);
    cudaFuncSetAttribute(gemm_v6<EPI_F32>,  cudaFuncAttributeMaxDynamicSharedMemorySize, G6_SMEM);
    cudaFuncSetAttribute(gemm_v6<EPI_GELU>, cudaFuncAttributeMaxDynamicSharedMemorySize, G6_SMEM);
    cudaFuncSetAttribute(attn_kernel,       cudaFuncAttributeMaxDynamicSharedMemorySize, ASMEM);

    // launch 0: fused prep
    prep_all<<<20480, 256>>>(x, w_attn, w_aproj, w_fc, w_mproj,
                             x16, wattnT, waprojT, wfcT, wmprojT);

    // launch 1: qkv (N = 3072, K = 1024)
    gemm_v6<EPI_QKV><<<dim3(3 * DMODEL / 64, ROWS / 128), 256, G6_SMEM>>>(
        x16, wattnT, b_attn, nullptr, nullptr, q16, k16, v16, 3 * DMODEL, DMODEL);

    // launch 2: attention
    attn_kernel<<<dim3(SEQ / 128, BATCH * NHEAD), 256, ASMEM>>>(q16, k16, v16, a16);

    // launch 3: aproj (N = K = 1024)
    gemm_v6<EPI_F32><<<dim3(DMODEL / 64, ROWS / 128), 256, G6_SMEM>>>(
        a16, waprojT, b_aproj, ap32, nullptr, nullptr, nullptr, nullptr,
        DMODEL, DMODEL);

    // launch 4: n = LN(x + aproj)
    ln_kernel<<<ROWS, 256>>>(x, ap32, g1, b1, n32, n16);

    // launch 5: fc + gelu (N = 4096, K = 1024)   <- ncu -s 5 -c 1 captures this
    gemm_v6<EPI_GELU><<<dim3(DFF / 64, ROWS / 128), 256, G6_SMEM>>>(
        n16, wfcT, b_fc, nullptr, h16, nullptr, nullptr, nullptr,
        DFF, DMODEL);

    // launch 6: mproj (N = 1024, K = 4096)
    gemm_v6<EPI_F32><<<dim3(DMODEL / 64, ROWS / 128), 256, G6_SMEM>>>(
        h16, wmprojT, b_mproj, m32, nullptr, nullptr, nullptr, nullptr,
        DMODEL, DFF);

    // launch 7: out = LN(n + m)
    ln_kernel<<<ROWS, 256>>>(n32, m32, g2, b2, out, nullptr);
}

// round 15
// speedup vs baseline: 1.1620x; 1.0236x over previous
#include <cuda_runtime.h>
#include <cuda_fp16.h>
#include <cstdint>
#include <cstddef>

// ---------------------------------------------------------------------------
// GPT-2 transformer block. mma.sync + ldmatrix + cp.async. fp32 I/O, fp16
// compute, fp32 acc. R15 = R14 + attention restructured for 2 CTAs/SM
// (64-col softmax halves -> fewer regs, 2-stage smem, diagonal half-skip).
// ---------------------------------------------------------------------------

#define BATCH  4
#define SEQ    2048
#define DMODEL 1024
#define NHEAD  16
#define HDIM   64
#define DFF    4096
#define ROWS   (BATCH * SEQ)

// -------------------------- scratch (device globals) ----------------------
__device__ __half g_x16    [(size_t)ROWS * DMODEL];
__device__ __half g_wattnT [(size_t)3 * DMODEL * DMODEL];
__device__ __half g_waprojT[(size_t)DMODEL * DMODEL];
__device__ __half g_wfcT   [(size_t)DFF * DMODEL];
__device__ __half g_wmprojT[(size_t)DMODEL * DFF];
__device__ __half g_q16    [(size_t)ROWS * DMODEL];
__device__ __half g_k16    [(size_t)ROWS * DMODEL];
__device__ __half g_v16    [(size_t)ROWS * DMODEL];
__device__ __half g_a16    [(size_t)ROWS * DMODEL];
__device__ float  g_ap32   [(size_t)ROWS * DMODEL];
__device__ float  g_n32    [(size_t)ROWS * DMODEL];
__device__ __half g_n16    [(size_t)ROWS * DMODEL];
__device__ __half g_h16    [(size_t)ROWS * DFF];
__device__ float  g_m32    [(size_t)ROWS * DMODEL];

// ------------------------------ helpers -----------------------------------
__device__ __forceinline__ void mma16816(float c[4], const uint32_t a[4],
                                         const uint32_t b[2]) {
    asm volatile(
        "mma.sync.aligned.m16n8k16.row.col.f32.f16.f16.f32 "
        "{%0,%1,%2,%3}, {%4,%5,%6,%7}, {%8,%9}, {%0,%1,%2,%3};\n"
        : "+f"(c[0]), "+f"(c[1]), "+f"(c[2]), "+f"(c[3])
        : "r"(a[0]), "r"(a[1]), "r"(a[2]), "r"(a[3]), "r"(b[0]), "r"(b[1]));
}

__device__ __forceinline__ void ldsm_x4(uint32_t r[4], uint32_t addr) {
    asm volatile("ldmatrix.sync.aligned.m8n8.x4.shared.b16 {%0,%1,%2,%3}, [%4];"
                 : "=r"(r[0]), "=r"(r[1]), "=r"(r[2]), "=r"(r[3]) : "r"(addr));
}

__device__ __forceinline__ void ldsm_x4_trans(uint32_t r[4], uint32_t addr) {
    asm volatile("ldmatrix.sync.aligned.m8n8.x4.trans.shared.b16 {%0,%1,%2,%3}, [%4];"
                 : "=r"(r[0]), "=r"(r[1]), "=r"(r[2]), "=r"(r[3]) : "r"(addr));
}

__device__ __forceinline__ void cp_async16(uint32_t smem, const void* gptr) {
    asm volatile("cp.async.cg.shared.global [%0], [%1], 16;\n" ::"r"(smem), "l"(gptr));
}
#define CP_COMMIT() asm volatile("cp.async.commit_group;\n" ::)
#define CP_WAIT(n)  asm volatile("cp.async.wait_group %0;\n" ::"n"(n))

__device__ __forceinline__ uint32_t smem_u32(const void* p) {
    uint32_t a;
    asm("{ .reg .u64 t; cvta.to.shared.u64 t, %1; cvt.u32.u64 %0, t; }"
        : "=r"(a) : "l"(p));
    return a;
}

__device__ __forceinline__ uint32_t pack_half2f(float a, float b) {
    __half2 h = __floats2half2_rn(a, b);
    return *reinterpret_cast<uint32_t*>(&h);
}

__device__ __forceinline__ float fast_exp2(float x) {
    float r;
    asm("ex2.approx.f32 %0, %1;" : "=f"(r) : "f"(x));
    return r;
}

__device__ __forceinline__ float gelu_f(float x) {
    const float k0 = 0.7978845608028654f;
    float u = k0 * (x + 0.044715f * x * x * x);
    float t;
    asm("tanh.approx.f32 %0, %1;" : "=f"(t) : "f"(u));
    return 0.5f * x * (1.0f + t);
}

// -------------------- fused prep: cvt + 4 weight transposes ----------------
__global__ __launch_bounds__(256) void prep_all(
    const float* __restrict__ x, const float* __restrict__ w_attn,
    const float* __restrict__ w_aproj, const float* __restrict__ w_fc,
    const float* __restrict__ w_mproj,
    __half* __restrict__ x16, __half* __restrict__ wattnT,
    __half* __restrict__ waprojT, __half* __restrict__ wfcT,
    __half* __restrict__ wmprojT) {
    int blk = blockIdx.x;
    const int tid = threadIdx.x;
    if (blk < 8192) {
        size_t off = (size_t)blk * DMODEL;
        float4 v = reinterpret_cast<const float4*>(x + off)[tid];
        __half2 h0 = __floats2half2_rn(v.x, v.y);
        __half2 h1 = __floats2half2_rn(v.z, v.w);
        *reinterpret_cast<uint2*>(x16 + off + tid * 4) =
            make_uint2(*reinterpret_cast<uint32_t*>(&h0),
                       *reinterpret_cast<uint32_t*>(&h1));
        return;
    }
    blk -= 8192;
    const float* src;
    __half* dst;
    int R, C;
    if (blk < 3072)      { src = w_attn;  dst = wattnT;  R = 1024; C = 3072; }
    else if (blk < 4096) { blk -= 3072; src = w_aproj; dst = waprojT; R = 1024; C = 1024; }
    else if (blk < 8192) { blk -= 4096; src = w_fc;    dst = wfcT;    R = 1024; C = 4096; }
    else                 { blk -= 8192; src = w_mproj; dst = wmprojT; R = 4096; C = 1024; }
    const int tilesX = C / 32;
    const int tx = blk % tilesX, ty = blk / tilesX;
    __shared__ float t[32][33];
    {
        const int row = tid >> 3, c4 = (tid & 7) * 4;
        float4 v = *reinterpret_cast<const float4*>(
            &src[(size_t)(ty * 32 + row) * C + tx * 32 + c4]);
        t[row][c4 + 0] = v.x;
        t[row][c4 + 1] = v.y;
        t[row][c4 + 2] = v.z;
        t[row][c4 + 3] = v.w;
    }
    __syncthreads();
    const int ox = tid & 15, oyb = tid >> 4;
#pragma unroll
    for (int i = 0; i < 32; i += 16) {
        int rr = oyb + i;
        uint32_t h = pack_half2f(t[2 * ox][rr], t[2 * ox + 1][rr]);
        *reinterpret_cast<uint32_t*>(
            &dst[(size_t)(tx * 32 + rr) * R + ty * 32 + 2 * ox]) = h;
    }
}

// ------------------------------- GEMM v6 -----------------------------------
// C[M,N] = A[M,K](f16 rm) * Bt[N,K](f16) + bias. CTA 128x64, 256 threads
// (4m x 2n warps, warp tile 32x32), BK=64, 2 stages, 3 CTAs/SM (24 warps).
#define G6_BK   64
#define G6_LKB  144                    // 64 halves + pad (stride/16 = 9, odd)
#define G6_AST  (128 * G6_LKB)         // 18432 B
#define G6_BST  (64 * G6_LKB)          // 9216 B
#define G6_STG  (G6_AST + G6_BST)      // 27648 B
#define G6_SMEM (2 * G6_STG)           // 55296 B

enum { EPI_QKV = 0, EPI_F32 = 1, EPI_GELU = 2 };

template <int EPI>
__global__ __launch_bounds__(256, 3) void gemm_v6(
    const __half* __restrict__ A, const __half* __restrict__ Bt,
    const float* __restrict__ bias,
    float* __restrict__ outF, __half* __restrict__ outH,
    __half* __restrict__ oq, __half* __restrict__ ok, __half* __restrict__ ov,
    int N, int K) {
    extern __shared__ __align__(128) char smem[];
    const uint32_t sb = smem_u32(smem);

    const int tid  = threadIdx.x;
    const int warp = tid >> 5, lane = tid & 31;
    const int g = lane >> 2, tg = lane & 3;
    const int wm = warp >> 1, wn = warp & 1;
    const int bm = blockIdx.y * 128, bn = blockIdx.x * 64;
    const int KT = K / G6_BK;

    float acc[2][4][4];
#pragma unroll
    for (int i = 0; i < 2; i++)
#pragma unroll
        for (int j = 0; j < 4; j++)
#pragma unroll
            for (int q = 0; q < 4; q++) acc[i][j][q] = 0.f;

    const uint32_t a_lm = (uint32_t)((wm * 32 + (lane & 15)) * G6_LKB +
                                     (lane >> 4) * 16);
    const uint32_t b_lm = (uint32_t)(G6_AST +
        (wn * 32 + (lane & 7) + ((lane >> 4) << 3)) * G6_LKB +
        ((lane >> 3) & 1) * 16);

    auto load_tile = [&](int kt, int s) {
        const int k0 = kt * G6_BK;
        const uint32_t base = sb + s * G6_STG;
#pragma unroll
        for (int i = 0; i < 4; i++) {
            int idx = tid + i * 256;
            int row = idx >> 3, c = idx & 7;
            cp_async16(base + row * G6_LKB + c * 16,
                       &A[(size_t)(bm + row) * K + k0 + c * 8]);
        }
#pragma unroll
        for (int i = 0; i < 2; i++) {
            int idx = tid + i * 256;
            int row = idx >> 3, c = idx & 7;
            cp_async16(base + G6_AST + row * G6_LKB + c * 16,
                       &Bt[(size_t)(bn + row) * K + k0 + c * 8]);
        }
        CP_COMMIT();
    };

    load_tile(0, 0);

    for (int t = 0; t < KT; t++) {
        CP_WAIT(0);
        __syncthreads();
        if (t + 1 < KT) load_tile(t + 1, (t + 1) & 1);

        const uint32_t stg = sb + (t & 1) * G6_STG;
#pragma unroll
        for (int kk = 0; kk < 4; kk++) {
            uint32_t a0[4], a1[4], b[4][2];
            ldsm_x4(a0, stg + a_lm + kk * 32);
            ldsm_x4(a1, stg + a_lm + 16 * G6_LKB + kk * 32);
#pragma unroll
            for (int p = 0; p < 2; p++) {
                uint32_t r[4];
                ldsm_x4(r, stg + b_lm + p * 16 * G6_LKB + kk * 32);
                b[p * 2][0] = r[0]; b[p * 2][1] = r[1];
                b[p * 2 + 1][0] = r[2]; b[p * 2 + 1][1] = r[3];
            }
#pragma unroll
            for (int ni = 0; ni < 4; ni++) {
                mma16816(acc[0][ni], a0, b[ni]);
                mma16816(acc[1][ni], a1, b[ni]);
            }
        }
    }

    // ------------------------------ epilogue -------------------------------
#pragma unroll
    for (int mi = 0; mi < 2; mi++) {
        int r0 = bm + wm * 32 + mi * 16 + g;
        int r1 = r0 + 8;
#pragma unroll
        for (int ni = 0; ni < 4; ni++) {
            int c0 = bn + wn * 32 + ni * 8 + tg * 2;
            float bv0 = __ldg(&bias[c0]), bv1 = __ldg(&bias[c0 + 1]);
            float v00 = acc[mi][ni][0] + bv0, v01 = acc[mi][ni][1] + bv1;
            float v10 = acc[mi][ni][2] + bv0, v11 = acc[mi][ni][3] + bv1;
            if (EPI == EPI_F32) {
                *reinterpret_cast<float2*>(&outF[(size_t)r0 * N + c0]) =
                    make_float2(v00, v01);
                *reinterpret_cast<float2*>(&outF[(size_t)r1 * N + c0]) =
                    make_float2(v10, v11);
            } else if (EPI == EPI_GELU) {
                *reinterpret_cast<uint32_t*>(&outH[(size_t)r0 * N + c0]) =
                    pack_half2f(gelu_f(v00), gelu_f(v01));
                *reinterpret_cast<uint32_t*>(&outH[(size_t)r1 * N + c0]) =
                    pack_half2f(gelu_f(v10), gelu_f(v11));
            } else {  // EPI_QKV: scatter into per-head [B*H][S][hd]
                int which = c0 >> 10;
                int cc = c0 & 1023;
                int h = cc >> 6, d0 = cc & 63;
                __half* dst = which == 0 ? oq : which == 1 ? ok : ov;
                int b0i = r0 >> 11, s0i = r0 & 2047;
                int b1i = r1 >> 11, s1i = r1 & 2047;
                size_t i0 = ((size_t)(b0i * NHEAD + h) * SEQ + s0i) * HDIM + d0;
                size_t i1 = ((size_t)(b1i * NHEAD + h) * SEQ + s1i) * HDIM + d0;
                *reinterpret_cast<uint32_t*>(&dst[i0]) = pack_half2f(v00, v01);
                *reinterpret_cast<uint32_t*>(&dst[i1]) = pack_half2f(v10, v11);
            }
        }
    }
}

// --------------------------- flash attention v4 ----------------------------
// grid (S/128, B*H), 256 threads (8 warps x 16 q rows). Causal. 2-stage
// cp.async (gemm_v6 ordering), softmax over 64-col halves (fewer regs),
// diagonal half-1 skip for warps 0-3. 2 CTAs/SM.
#define AT_LKB 144
#define AT_KS  (128 * AT_LKB)         // 18432 B
#define AT_STG (2 * AT_KS)            // 36864 B (K + V)
#define ASMEM  (2 * AT_STG)           // 73728 B

__global__ __launch_bounds__(256, 2) void attn_kernel(
    const __half* __restrict__ Q, const __half* __restrict__ K,
    const __half* __restrict__ V, __half* __restrict__ Aout) {
    extern __shared__ __align__(128) char smem[];
    const uint32_t sb = smem_u32(smem);

    const int tid  = threadIdx.x;
    const int warp = tid >> 5, lane = tid & 31;
    const int g = lane >> 2, tg = lane & 3;
    const int bh = blockIdx.y;
    const int qb = blockIdx.x;
    const size_t base = (size_t)bh * SEQ * HDIM;

    auto load_kv = [&](int kb, int s) {
        const uint32_t bs = sb + s * AT_STG;
#pragma unroll
        for (int i = 0; i < 4; i++) {
            int idx = tid + i * 256;
            int row = idx >> 3, c = idx & 7;
            cp_async16(bs + row * AT_LKB + c * 16,
                       &K[base + (size_t)(kb * 128 + row) * HDIM + c * 8]);
        }
#pragma unroll
        for (int i = 0; i < 4; i++) {
            int idx = tid + i * 256;
            int row = idx >> 3, c = idx & 7;
            cp_async16(bs + AT_KS + row * AT_LKB + c * 16,
                       &V[base + (size_t)(kb * 128 + row) * HDIM + c * 8]);
        }
        CP_COMMIT();
    };

    load_kv(0, 0);

    // stage Q into stage-1 K area; frags lifted before stage 1 is loaded
#pragma unroll
    for (int i = 0; i < 4; i++) {
        int idx = tid + i * 256;
        int row = idx >> 3, c = idx & 7;
        *reinterpret_cast<uint4*>(smem + AT_STG + row * AT_LKB + c * 16) =
            *reinterpret_cast<const uint4*>(
                &Q[base + (size_t)(qb * 128 + row) * HDIM + c * 8]);
    }
    __syncthreads();
    uint32_t qa[4][4];
    {
        const uint32_t q_lm = sb + AT_STG +
            (warp * 16 + (lane & 15)) * AT_LKB + (lane >> 4) * 16;
#pragma unroll
        for (int kt = 0; kt < 4; kt++) ldsm_x4(qa[kt], q_lm + kt * 32);
    }
    __syncthreads();   // all warps finished lifting before stage 1 is reused

    const uint32_t k_lm = (uint32_t)(((lane & 7) + ((lane >> 4) << 3)) * AT_LKB +
                                     ((lane >> 3) & 1) * 16);
    const uint32_t v_lm = (uint32_t)(((lane & 7) + (((lane >> 3) & 1) << 3)) * AT_LKB +
                                     (lane >> 4) * 16);

    float o[8][4];
#pragma unroll
    for (int i = 0; i < 8; i++)
#pragma unroll
        for (int j = 0; j < 4; j++) o[i][j] = 0.f;
    float m0 = -1e30f, m1 = -1e30f, l0 = 0.f, l1 = 0.f;
    const int q0 = qb * 128 + warp * 16 + g;
    const int q1 = q0 + 8;

    int stage = 0;
    for (int kblk = 0; kblk <= qb; kblk++) {
        CP_WAIT(0);
        __syncthreads();
        if (kblk < qb) load_kv(kblk + 1, stage ^ 1);

        const uint32_t ks = sb + stage * AT_STG;
        const uint32_t vs = ks + AT_KS;
        const float scale = 0.18033688011112042f;  // rsqrt(64)*log2(e)

#pragma unroll
        for (int half = 0; half < 2; half++) {
            // diagonal: half 1 fully masked for warps 0-3 (cols >= 64 > q rows)
            if (kblk == qb && half == 1 && warp < 4) continue;
            const int cb = kblk * 128 + half * 64;

            // S = Q K^T over 64 columns
            float sacc[8][4];
#pragma unroll
            for (int nt = 0; nt < 8; nt++)
#pragma unroll
                for (int j = 0; j < 4; j++) sacc[nt][j] = 0.f;
#pragma unroll
            for (int kt = 0; kt < 4; kt++) {
#pragma unroll
                for (int pair = 0; pair < 4; pair++) {
                    uint32_t r[4];
                    ldsm_x4(r, ks + k_lm +
                               (half * 4 + pair) * 16 * AT_LKB + kt * 32);
                    mma16816(sacc[pair * 2],     qa[kt], r);
                    mma16816(sacc[pair * 2 + 1], qa[kt], r + 2);
                }
            }

            // scale + causal mask
#pragma unroll
            for (int nt = 0; nt < 8; nt++) {
                int c0 = cb + nt * 8 + tg * 2;
                sacc[nt][0] *= scale; sacc[nt][1] *= scale;
                sacc[nt][2] *= scale; sacc[nt][3] *= scale;
                if (kblk == qb) {
                    if (c0 > q0)     sacc[nt][0] = -1e30f;
                    if (c0 + 1 > q0) sacc[nt][1] = -1e30f;
                    if (c0 > q1)     sacc[nt][2] = -1e30f;
                    if (c0 + 1 > q1) sacc[nt][3] = -1e30f;
                }
            }

            // online softmax (per 64-col half)
            float nm0 = m0, nm1 = m1;
#pragma unroll
            for (int nt = 0; nt < 8; nt++) {
                nm0 = fmaxf(nm0, fmaxf(sacc[nt][0], sacc[nt][1]));
                nm1 = fmaxf(nm1, fmaxf(sacc[nt][2], sacc[nt][3]));
            }
            nm0 = fmaxf(nm0, __shfl_xor_sync(0xffffffffu, nm0, 1));
            nm0 = fmaxf(nm0, __shfl_xor_sync(0xffffffffu, nm0, 2));
            nm1 = fmaxf(nm1, __shfl_xor_sync(0xffffffffu, nm1, 1));
            nm1 = fmaxf(nm1, __shfl_xor_sync(0xffffffffu, nm1, 2));
            float alpha0 = fast_exp2(m0 - nm0), alpha1 = fast_exp2(m1 - nm1);

            float ls0 = 0.f, ls1 = 0.f;
            uint32_t pa[4][4];
#pragma unroll
            for (int nt = 0; nt < 8; nt++) {
                __half2 e0 = h2exp2(__floats2half2_rn(sacc[nt][0] - nm0,
                                                      sacc[nt][1] - nm0));
                __half2 e1 = h2exp2(__floats2half2_rn(sacc[nt][2] - nm1,
                                                      sacc[nt][3] - nm1));
                float2 f0 = __half22float2(e0);
                float2 f1 = __half22float2(e1);
                ls0 += f0.x + f0.y;
                ls1 += f1.x + f1.y;
                int kt = nt >> 1, hi = nt & 1;
                pa[kt][hi * 2 + 0] = *reinterpret_cast<uint32_t*>(&e0);
                pa[kt][hi * 2 + 1] = *reinterpret_cast<uint32_t*>(&e1);
            }
            ls0 += __shfl_xor_sync(0xffffffffu, ls0, 1);
            ls0 += __shfl_xor_sync(0xffffffffu, ls0, 2);
            ls1 += __shfl_xor_sync(0xffffffffu, ls1, 1);
            ls1 += __shfl_xor_sync(0xffffffffu, ls1, 2);
            l0 = l0 * alpha0 + ls0;
            l1 = l1 * alpha1 + ls1;
            m0 = nm0;
            m1 = nm1;
#pragma unroll
            for (int dnt = 0; dnt < 8; dnt++) {
                o[dnt][0] *= alpha0; o[dnt][1] *= alpha0;
                o[dnt][2] *= alpha1; o[dnt][3] *= alpha1;
            }

            // O += P V over the 64 rows of this half
#pragma unroll
            for (int kt = 0; kt < 4; kt++) {
#pragma unroll
                for (int dp = 0; dp < 4; dp++) {
                    uint32_t r[4];
                    ldsm_x4_trans(r, vs + v_lm +
                                     (half * 4 + kt) * 16 * AT_LKB + dp * 32);
                    mma16816(o[dp * 2],     pa[kt], r);
                    mma16816(o[dp * 2 + 1], pa[kt], r + 2);
                }
            }
        }
        stage ^= 1;
    }

    float inv0 = 1.f / l0, inv1 = 1.f / l1;
    int b = bh >> 4, h = bh & 15;
    int s0 = qb * 128 + warp * 16 + g;
    size_t r0 = (size_t)(b * SEQ + s0) * DMODEL + h * HDIM;
    size_t r1 = r0 + (size_t)8 * DMODEL;
#pragma unroll
    for (int dnt = 0; dnt < 8; dnt++) {
        int d = dnt * 8 + tg * 2;
        *reinterpret_cast<uint32_t*>(&Aout[r0 + d]) =
            pack_half2f(o[dnt][0] * inv0, o[dnt][1] * inv0);
        *reinterpret_cast<uint32_t*>(&Aout[r1 + d]) =
            pack_half2f(o[dnt][2] * inv1, o[dnt][3] * inv1);
    }
}

// --------------------------- residual + layernorm --------------------------
__global__ __launch_bounds__(256) void ln_kernel(
    const float* __restrict__ X, const float* __restrict__ Y,
    const float* __restrict__ gg, const float* __restrict__ bb,
    float* __restrict__ out32, __half* __restrict__ out16) {
    const int row = blockIdx.x, tid = threadIdx.x;
    const size_t roff = (size_t)row * DMODEL;
    float4 xv = reinterpret_cast<const float4*>(X + roff)[tid];
    float4 yv = reinterpret_cast<const float4*>(Y + roff)[tid];
    float v[4] = {xv.x + yv.x, xv.y + yv.y, xv.z + yv.z, xv.w + yv.w};
    float s = v[0] + v[1] + v[2] + v[3];

    __shared__ float red[8], red2[8];
#pragma unroll
    for (int o = 16; o; o >>= 1) s += __shfl_xor_sync(0xffffffffu, s, o);
    if ((tid & 31) == 0) red[tid >> 5] = s;
    __syncthreads();
    float tot = 0.f;
#pragma unroll
    for (int i = 0; i < 8; i++) tot += red[i];
    float mean = tot * (1.0f / DMODEL);

    float s2 = 0.f;
#pragma unroll
    for (int i = 0; i < 4; i++) {
        float d = v[i] - mean;
        s2 += d * d;
    }
#pragma unroll
    for (int o = 16; o; o >>= 1) s2 += __shfl_xor_sync(0xffffffffu, s2, o);
    if ((tid & 31) == 0) red2[tid >> 5] = s2;
    __syncthreads();
    float tot2 = 0.f;
#pragma unroll
    for (int i = 0; i < 8; i++) tot2 += red2[i];
    float rstd = rsqrtf(tot2 * (1.0f / DMODEL) + 1e-5f);

    float4 gv = reinterpret_cast<const float4*>(gg)[tid];
    float4 bv = reinterpret_cast<const float4*>(bb)[tid];
    float4 nv;
    nv.x = (v[0] - mean) * rstd * gv.x + bv.x;
    nv.y = (v[1] - mean) * rstd * gv.y + bv.y;
    nv.z = (v[2] - mean) * rstd * gv.z + bv.z;
    nv.w = (v[3] - mean) * rstd * gv.w + bv.w;
    reinterpret_cast<float4*>(out32 + roff)[tid] = nv;
    if (out16) {
        *reinterpret_cast<uint2*>(out16 + roff + tid * 4) =
            make_uint2(pack_half2f(nv.x, nv.y), pack_half2f(nv.z, nv.w));
    }
}

// ------------------------------- host --------------------------------------
extern "C" void kernel_launch(void* const* d_in, const int* in_sizes, int n_in,
                              void* d_out, int out_size) {
    const float* x       = (const float*)d_in[0];
    const float* w_attn  = (const float*)d_in[1];
    const float* b_attn  = (const float*)d_in[2];
    const float* w_aproj = (const float*)d_in[3];
    const float* b_aproj = (const float*)d_in[4];
    const float* g1      = (const float*)d_in[5];
    const float* b1      = (const float*)d_in[6];
    const float* w_fc    = (const float*)d_in[7];
    const float* b_fc    = (const float*)d_in[8];
    const float* w_mproj = (const float*)d_in[9];
    const float* b_mproj = (const float*)d_in[10];
    const float* g2      = (const float*)d_in[11];
    const float* b2      = (const float*)d_in[12];
    float* out = (float*)d_out;

    __half *x16, *wattnT, *waprojT, *wfcT, *wmprojT, *q16, *k16, *v16, *a16, *n16, *h16;
    float *ap32, *n32, *m32;
    cudaGetSymbolAddress((void**)&x16,     g_x16);
    cudaGetSymbolAddress((void**)&wattnT,  g_wattnT);
    cudaGetSymbolAddress((void**)&waprojT, g_waprojT);
    cudaGetSymbolAddress((void**)&wfcT,    g_wfcT);
    cudaGetSymbolAddress((void**)&wmprojT, g_wmprojT);
    cudaGetSymbolAddress((void**)&q16,     g_q16);
    cudaGetSymbolAddress((void**)&k16,     g_k16);
    cudaGetSymbolAddress((void**)&v16,     g_v16);
    cudaGetSymbolAddress((void**)&a16,     g_a16);
    cudaGetSymbolAddress((void**)&n16,     g_n16);
    cudaGetSymbolAddress((void**)&h16,     g_h16);
    cudaGetSymbolAddress((void**)&ap32,    g_ap32);
    cudaGetSymbolAddress((void**)&n32,     g_n32);
    cudaGetSymbolAddress((void**)&m32,     g_m32);

    cudaFuncSetAttribute(gemm_v6<EPI_QKV>,  cudaFuncAttributeMaxDynamicSharedMemorySize, G6_SMEM);
    cudaFuncSetAttribute(gemm_v6<EPI_F32>,  cudaFuncAttributeMaxDynamicSharedMemorySize, G6_SMEM);
    cudaFuncSetAttribute(gemm_v6<EPI_GELU>, cudaFuncAttributeMaxDynamicSharedMemorySize, G6_SMEM);
    cudaFuncSetAttribute(attn_kernel,       cudaFuncAttributeMaxDynamicSharedMemorySize, ASMEM);

    // launch 0: fused prep
    prep_all<<<20480, 256>>>(x, w_attn, w_aproj, w_fc, w_mproj,
                             x16, wattnT, waprojT, wfcT, wmprojT);

    // launch 1: qkv (N = 3072, K = 1024)
    gemm_v6<EPI_QKV><<<dim3(3 * DMODEL / 64, ROWS / 128), 256, G6_SMEM>>>(
        x16, wattnT, b_attn, nullptr, nullptr, q16, k16, v16, 3 * DMODEL, DMODEL);

    // launch 2: attention
    attn_kernel<<<dim3(SEQ / 128, BATCH * NHEAD), 256, ASMEM>>>(q16, k16, v16, a16);

    // launch 3: aproj (N = K = 1024)
    gemm_v6<EPI_F32><<<dim3(DMODEL / 64, ROWS / 128), 256, G6_SMEM>>>(
        a16, waprojT, b_aproj, ap32, nullptr, nullptr, nullptr, nullptr,
        DMODEL, DMODEL);

    // launch 4: n = LN(x + aproj)
    ln_kernel<<<ROWS, 256>>>(x, ap32, g1, b1, n32, n16);

    // launch 5: fc + gelu (N = 4096, K = 1024)   <- ncu -s 5 -c 1 captures this
    gemm_v6<EPI_GELU><<<dim3(DFF / 64, ROWS / 128), 256, G6_SMEM>>>(
        n16, wfcT, b_fc, nullptr, h16, nullptr, nullptr, nullptr,
        DFF, DMODEL);

    // launch 6: mproj (N = 1024, K = 4096)
    gemm_v6<EPI_F32><<<dim3(DMODEL / 64, ROWS / 128), 256, G6_SMEM>>>(
        h16, wmprojT, b_mproj, m32, nullptr, nullptr, nullptr, nullptr,
        DMODEL, DFF);

    // launch 7: out = LN(n + m)
    ln_kernel<<<ROWS, 256>>>(n32, m32, g2, b2, out, nullptr);
}

// round 16
// speedup vs baseline: 1.2063x; 1.0381x over previous
#include <cuda_runtime.h>
#include <cuda_fp16.h>
#include <cstdint>
#include <cstddef>

// ---------------------------------------------------------------------------
// GPT-2 transformer block. mma.sync + ldmatrix + cp.async. fp32 I/O, fp16
// compute, fp32 acc. R16 = R15 (best 848us) + longest-first attention
// scheduling (1-D grid, qb descending) to pack the triangular work tail.
// ---------------------------------------------------------------------------

#define BATCH  4
#define SEQ    2048
#define DMODEL 1024
#define NHEAD  16
#define HDIM   64
#define DFF    4096
#define ROWS   (BATCH * SEQ)

// -------------------------- scratch (device globals) ----------------------
__device__ __half g_x16    [(size_t)ROWS * DMODEL];
__device__ __half g_wattnT [(size_t)3 * DMODEL * DMODEL];
__device__ __half g_waprojT[(size_t)DMODEL * DMODEL];
__device__ __half g_wfcT   [(size_t)DFF * DMODEL];
__device__ __half g_wmprojT[(size_t)DMODEL * DFF];
__device__ __half g_q16    [(size_t)ROWS * DMODEL];
__device__ __half g_k16    [(size_t)ROWS * DMODEL];
__device__ __half g_v16    [(size_t)ROWS * DMODEL];
__device__ __half g_a16    [(size_t)ROWS * DMODEL];
__device__ float  g_ap32   [(size_t)ROWS * DMODEL];
__device__ float  g_n32    [(size_t)ROWS * DMODEL];
__device__ __half g_n16    [(size_t)ROWS * DMODEL];
__device__ __half g_h16    [(size_t)ROWS * DFF];
__device__ float  g_m32    [(size_t)ROWS * DMODEL];

// ------------------------------ helpers -----------------------------------
__device__ __forceinline__ void mma16816(float c[4], const uint32_t a[4],
                                         const uint32_t b[2]) {
    asm volatile(
        "mma.sync.aligned.m16n8k16.row.col.f32.f16.f16.f32 "
        "{%0,%1,%2,%3}, {%4,%5,%6,%7}, {%8,%9}, {%0,%1,%2,%3};\n"
        : "+f"(c[0]), "+f"(c[1]), "+f"(c[2]), "+f"(c[3])
        : "r"(a[0]), "r"(a[1]), "r"(a[2]), "r"(a[3]), "r"(b[0]), "r"(b[1]));
}

__device__ __forceinline__ void ldsm_x4(uint32_t r[4], uint32_t addr) {
    asm volatile("ldmatrix.sync.aligned.m8n8.x4.shared.b16 {%0,%1,%2,%3}, [%4];"
                 : "=r"(r[0]), "=r"(r[1]), "=r"(r[2]), "=r"(r[3]) : "r"(addr));
}

__device__ __forceinline__ void ldsm_x4_trans(uint32_t r[4], uint32_t addr) {
    asm volatile("ldmatrix.sync.aligned.m8n8.x4.trans.shared.b16 {%0,%1,%2,%3}, [%4];"
                 : "=r"(r[0]), "=r"(r[1]), "=r"(r[2]), "=r"(r[3]) : "r"(addr));
}

__device__ __forceinline__ void cp_async16(uint32_t smem, const void* gptr) {
    asm volatile("cp.async.cg.shared.global [%0], [%1], 16;\n" ::"r"(smem), "l"(gptr));
}
#define CP_COMMIT() asm volatile("cp.async.commit_group;\n" ::)
#define CP_WAIT(n)  asm volatile("cp.async.wait_group %0;\n" ::"n"(n))

__device__ __forceinline__ uint32_t smem_u32(const void* p) {
    uint32_t a;
    asm("{ .reg .u64 t; cvta.to.shared.u64 t, %1; cvt.u32.u64 %0, t; }"
        : "=r"(a) : "l"(p));
    return a;
}

__device__ __forceinline__ uint32_t pack_half2f(float a, float b) {
    __half2 h = __floats2half2_rn(a, b);
    return *reinterpret_cast<uint32_t*>(&h);
}

__device__ __forceinline__ float fast_exp2(float x) {
    float r;
    asm("ex2.approx.f32 %0, %1;" : "=f"(r) : "f"(x));
    return r;
}

__device__ __forceinline__ float gelu_f(float x) {
    const float k0 = 0.7978845608028654f;
    float u = k0 * (x + 0.044715f * x * x * x);
    float t;
    asm("tanh.approx.f32 %0, %1;" : "=f"(t) : "f"(u));
    return 0.5f * x * (1.0f + t);
}

// -------------------- fused prep: cvt + 4 weight transposes ----------------
__global__ __launch_bounds__(256) void prep_all(
    const float* __restrict__ x, const float* __restrict__ w_attn,
    const float* __restrict__ w_aproj, const float* __restrict__ w_fc,
    const float* __restrict__ w_mproj,
    __half* __restrict__ x16, __half* __restrict__ wattnT,
    __half* __restrict__ waprojT, __half* __restrict__ wfcT,
    __half* __restrict__ wmprojT) {
    int blk = blockIdx.x;
    const int tid = threadIdx.x;
    if (blk < 8192) {
        size_t off = (size_t)blk * DMODEL;
        float4 v = reinterpret_cast<const float4*>(x + off)[tid];
        __half2 h0 = __floats2half2_rn(v.x, v.y);
        __half2 h1 = __floats2half2_rn(v.z, v.w);
        *reinterpret_cast<uint2*>(x16 + off + tid * 4) =
            make_uint2(*reinterpret_cast<uint32_t*>(&h0),
                       *reinterpret_cast<uint32_t*>(&h1));
        return;
    }
    blk -= 8192;
    const float* src;
    __half* dst;
    int R, C;
    if (blk < 3072)      { src = w_attn;  dst = wattnT;  R = 1024; C = 3072; }
    else if (blk < 4096) { blk -= 3072; src = w_aproj; dst = waprojT; R = 1024; C = 1024; }
    else if (blk < 8192) { blk -= 4096; src = w_fc;    dst = wfcT;    R = 1024; C = 4096; }
    else                 { blk -= 8192; src = w_mproj; dst = wmprojT; R = 4096; C = 1024; }
    const int tilesX = C / 32;
    const int tx = blk % tilesX, ty = blk / tilesX;
    __shared__ float t[32][33];
    {
        const int row = tid >> 3, c4 = (tid & 7) * 4;
        float4 v = *reinterpret_cast<const float4*>(
            &src[(size_t)(ty * 32 + row) * C + tx * 32 + c4]);
        t[row][c4 + 0] = v.x;
        t[row][c4 + 1] = v.y;
        t[row][c4 + 2] = v.z;
        t[row][c4 + 3] = v.w;
    }
    __syncthreads();
    const int ox = tid & 15, oyb = tid >> 4;
#pragma unroll
    for (int i = 0; i < 32; i += 16) {
        int rr = oyb + i;
        uint32_t h = pack_half2f(t[2 * ox][rr], t[2 * ox + 1][rr]);
        *reinterpret_cast<uint32_t*>(
            &dst[(size_t)(tx * 32 + rr) * R + ty * 32 + 2 * ox]) = h;
    }
}

// ------------------------------- GEMM v6 -----------------------------------
// C[M,N] = A[M,K](f16 rm) * Bt[N,K](f16) + bias. CTA 128x64, 256 threads
// (4m x 2n warps, warp tile 32x32), BK=64, 2 stages, 3 CTAs/SM (24 warps).
#define G6_BK   64
#define G6_LKB  144                    // 64 halves + pad (stride/16 = 9, odd)
#define G6_AST  (128 * G6_LKB)         // 18432 B
#define G6_BST  (64 * G6_LKB)          // 9216 B
#define G6_STG  (G6_AST + G6_BST)      // 27648 B
#define G6_SMEM (2 * G6_STG)           // 55296 B

enum { EPI_QKV = 0, EPI_F32 = 1, EPI_GELU = 2 };

template <int EPI>
__global__ __launch_bounds__(256, 3) void gemm_v6(
    const __half* __restrict__ A, const __half* __restrict__ Bt,
    const float* __restrict__ bias,
    float* __restrict__ outF, __half* __restrict__ outH,
    __half* __restrict__ oq, __half* __restrict__ ok, __half* __restrict__ ov,
    int N, int K) {
    extern __shared__ __align__(128) char smem[];
    const uint32_t sb = smem_u32(smem);

    const int tid  = threadIdx.x;
    const int warp = tid >> 5, lane = tid & 31;
    const int g = lane >> 2, tg = lane & 3;
    const int wm = warp >> 1, wn = warp & 1;
    const int bm = blockIdx.y * 128, bn = blockIdx.x * 64;
    const int KT = K / G6_BK;

    float acc[2][4][4];
#pragma unroll
    for (int i = 0; i < 2; i++)
#pragma unroll
        for (int j = 0; j < 4; j++)
#pragma unroll
            for (int q = 0; q < 4; q++) acc[i][j][q] = 0.f;

    const uint32_t a_lm = (uint32_t)((wm * 32 + (lane & 15)) * G6_LKB +
                                     (lane >> 4) * 16);
    const uint32_t b_lm = (uint32_t)(G6_AST +
        (wn * 32 + (lane & 7) + ((lane >> 4) << 3)) * G6_LKB +
        ((lane >> 3) & 1) * 16);

    auto load_tile = [&](int kt, int s) {
        const int k0 = kt * G6_BK;
        const uint32_t base = sb + s * G6_STG;
#pragma unroll
        for (int i = 0; i < 4; i++) {
            int idx = tid + i * 256;
            int row = idx >> 3, c = idx & 7;
            cp_async16(base + row * G6_LKB + c * 16,
                       &A[(size_t)(bm + row) * K + k0 + c * 8]);
        }
#pragma unroll
        for (int i = 0; i < 2; i++) {
            int idx = tid + i * 256;
            int row = idx >> 3, c = idx & 7;
            cp_async16(base + G6_AST + row * G6_LKB + c * 16,
                       &Bt[(size_t)(bn + row) * K + k0 + c * 8]);
        }
        CP_COMMIT();
    };

    load_tile(0, 0);

    for (int t = 0; t < KT; t++) {
        CP_WAIT(0);
        __syncthreads();
        if (t + 1 < KT) load_tile(t + 1, (t + 1) & 1);

        const uint32_t stg = sb + (t & 1) * G6_STG;
#pragma unroll
        for (int kk = 0; kk < 4; kk++) {
            uint32_t a0[4], a1[4], b[4][2];
            ldsm_x4(a0, stg + a_lm + kk * 32);
            ldsm_x4(a1, stg + a_lm + 16 * G6_LKB + kk * 32);
#pragma unroll
            for (int p = 0; p < 2; p++) {
                uint32_t r[4];
                ldsm_x4(r, stg + b_lm + p * 16 * G6_LKB + kk * 32);
                b[p * 2][0] = r[0]; b[p * 2][1] = r[1];
                b[p * 2 + 1][0] = r[2]; b[p * 2 + 1][1] = r[3];
            }
#pragma unroll
            for (int ni = 0; ni < 4; ni++) {
                mma16816(acc[0][ni], a0, b[ni]);
                mma16816(acc[1][ni], a1, b[ni]);
            }
        }
    }

    // ------------------------------ epilogue -------------------------------
#pragma unroll
    for (int mi = 0; mi < 2; mi++) {
        int r0 = bm + wm * 32 + mi * 16 + g;
        int r1 = r0 + 8;
#pragma unroll
        for (int ni = 0; ni < 4; ni++) {
            int c0 = bn + wn * 32 + ni * 8 + tg * 2;
            float bv0 = __ldg(&bias[c0]), bv1 = __ldg(&bias[c0 + 1]);
            float v00 = acc[mi][ni][0] + bv0, v01 = acc[mi][ni][1] + bv1;
            float v10 = acc[mi][ni][2] + bv0, v11 = acc[mi][ni][3] + bv1;
            if (EPI == EPI_F32) {
                *reinterpret_cast<float2*>(&outF[(size_t)r0 * N + c0]) =
                    make_float2(v00, v01);
                *reinterpret_cast<float2*>(&outF[(size_t)r1 * N + c0]) =
                    make_float2(v10, v11);
            } else if (EPI == EPI_GELU) {
                *reinterpret_cast<uint32_t*>(&outH[(size_t)r0 * N + c0]) =
                    pack_half2f(gelu_f(v00), gelu_f(v01));
                *reinterpret_cast<uint32_t*>(&outH[(size_t)r1 * N + c0]) =
                    pack_half2f(gelu_f(v10), gelu_f(v11));
            } else {  // EPI_QKV: scatter into per-head [B*H][S][hd]
                int which = c0 >> 10;
                int cc = c0 & 1023;
                int h = cc >> 6, d0 = cc & 63;
                __half* dst = which == 0 ? oq : which == 1 ? ok : ov;
                int b0i = r0 >> 11, s0i = r0 & 2047;
                int b1i = r1 >> 11, s1i = r1 & 2047;
                size_t i0 = ((size_t)(b0i * NHEAD + h) * SEQ + s0i) * HDIM + d0;
                size_t i1 = ((size_t)(b1i * NHEAD + h) * SEQ + s1i) * HDIM + d0;
                *reinterpret_cast<uint32_t*>(&dst[i0]) = pack_half2f(v00, v01);
                *reinterpret_cast<uint32_t*>(&dst[i1]) = pack_half2f(v10, v11);
            }
        }
    }
}

// --------------------------- flash attention v4 ----------------------------
// grid 1024 (1-D, longest-first: qb = 15 - bx/64, bh = bx%64). 256 threads
// (8 warps x 16 q rows). Causal. 2-stage cp.async, 64-col softmax halves,
// diagonal half-1 skip for warps 0-3. 2 CTAs/SM.
#define AT_LKB 144
#define AT_KS  (128 * AT_LKB)         // 18432 B
#define AT_STG (2 * AT_KS)            // 36864 B (K + V)
#define ASMEM  (2 * AT_STG)           // 73728 B

__global__ __launch_bounds__(256, 2) void attn_kernel(
    const __half* __restrict__ Q, const __half* __restrict__ K,
    const __half* __restrict__ V, __half* __restrict__ Aout) {
    extern __shared__ __align__(128) char smem[];
    const uint32_t sb = smem_u32(smem);

    const int tid  = threadIdx.x;
    const int warp = tid >> 5, lane = tid & 31;
    const int g = lane >> 2, tg = lane & 3;
    // longest-first mapping: CTAs with the most K-blocks launch first
    const int qb = (SEQ / 128 - 1) - (blockIdx.x >> 6);
    const int bh = blockIdx.x & 63;
    const size_t base = (size_t)bh * SEQ * HDIM;

    auto load_kv = [&](int kb, int s) {
        const uint32_t bs = sb + s * AT_STG;
#pragma unroll
        for (int i = 0; i < 4; i++) {
            int idx = tid + i * 256;
            int row = idx >> 3, c = idx & 7;
            cp_async16(bs + row * AT_LKB + c * 16,
                       &K[base + (size_t)(kb * 128 + row) * HDIM + c * 8]);
        }
#pragma unroll
        for (int i = 0; i < 4; i++) {
            int idx = tid + i * 256;
            int row = idx >> 3, c = idx & 7;
            cp_async16(bs + AT_KS + row * AT_LKB + c * 16,
                       &V[base + (size_t)(kb * 128 + row) * HDIM + c * 8]);
        }
        CP_COMMIT();
    };

    load_kv(0, 0);

    // stage Q into stage-1 K area; frags lifted before stage 1 is loaded
#pragma unroll
    for (int i = 0; i < 4; i++) {
        int idx = tid + i * 256;
        int row = idx >> 3, c = idx & 7;
        *reinterpret_cast<uint4*>(smem + AT_STG + row * AT_LKB + c * 16) =
            *reinterpret_cast<const uint4*>(
                &Q[base + (size_t)(qb * 128 + row) * HDIM + c * 8]);
    }
    __syncthreads();
    uint32_t qa[4][4];
    {
        const uint32_t q_lm = sb + AT_STG +
            (warp * 16 + (lane & 15)) * AT_LKB + (lane >> 4) * 16;
#pragma unroll
        for (int kt = 0; kt < 4; kt++) ldsm_x4(qa[kt], q_lm + kt * 32);
    }
    __syncthreads();   // all warps finished lifting before stage 1 is reused

    const uint32_t k_lm = (uint32_t)(((lane & 7) + ((lane >> 4) << 3)) * AT_LKB +
                                     ((lane >> 3) & 1) * 16);
    const uint32_t v_lm = (uint32_t)(((lane & 7) + (((lane >> 3) & 1) << 3)) * AT_LKB +
                                     (lane >> 4) * 16);

    float o[8][4];
#pragma unroll
    for (int i = 0; i < 8; i++)
#pragma unroll
        for (int j = 0; j < 4; j++) o[i][j] = 0.f;
    float m0 = -1e30f, m1 = -1e30f, l0 = 0.f, l1 = 0.f;
    const int q0 = qb * 128 + warp * 16 + g;
    const int q1 = q0 + 8;

    int stage = 0;
    for (int kblk = 0; kblk <= qb; kblk++) {
        CP_WAIT(0);
        __syncthreads();
        if (kblk < qb) load_kv(kblk + 1, stage ^ 1);

        const uint32_t ks = sb + stage * AT_STG;
        const uint32_t vs = ks + AT_KS;
        const float scale = 0.18033688011112042f;  // rsqrt(64)*log2(e)

#pragma unroll
        for (int half = 0; half < 2; half++) {
            // diagonal: half 1 fully masked for warps 0-3 (cols >= 64 > q rows)
            if (kblk == qb && half == 1 && warp < 4) continue;
            const int cb = kblk * 128 + half * 64;

            // S = Q K^T over 64 columns
            float sacc[8][4];
#pragma unroll
            for (int nt = 0; nt < 8; nt++)
#pragma unroll
                for (int j = 0; j < 4; j++) sacc[nt][j] = 0.f;
#pragma unroll
            for (int kt = 0; kt < 4; kt++) {
#pragma unroll
                for (int pair = 0; pair < 4; pair++) {
                    uint32_t r[4];
                    ldsm_x4(r, ks + k_lm +
                               (half * 4 + pair) * 16 * AT_LKB + kt * 32);
                    mma16816(sacc[pair * 2],     qa[kt], r);
                    mma16816(sacc[pair * 2 + 1], qa[kt], r + 2);
                }
            }

            // scale + causal mask
#pragma unroll
            for (int nt = 0; nt < 8; nt++) {
                int c0 = cb + nt * 8 + tg * 2;
                sacc[nt][0] *= scale; sacc[nt][1] *= scale;
                sacc[nt][2] *= scale; sacc[nt][3] *= scale;
                if (kblk == qb) {
                    if (c0 > q0)     sacc[nt][0] = -1e30f;
                    if (c0 + 1 > q0) sacc[nt][1] = -1e30f;
                    if (c0 > q1)     sacc[nt][2] = -1e30f;
                    if (c0 + 1 > q1) sacc[nt][3] = -1e30f;
                }
            }

            // online softmax (per 64-col half)
            float nm0 = m0, nm1 = m1;
#pragma unroll
            for (int nt = 0; nt < 8; nt++) {
                nm0 = fmaxf(nm0, fmaxf(sacc[nt][0], sacc[nt][1]));
                nm1 = fmaxf(nm1, fmaxf(sacc[nt][2], sacc[nt][3]));
            }
            nm0 = fmaxf(nm0, __shfl_xor_sync(0xffffffffu, nm0, 1));
            nm0 = fmaxf(nm0, __shfl_xor_sync(0xffffffffu, nm0, 2));
            nm1 = fmaxf(nm1, __shfl_xor_sync(0xffffffffu, nm1, 1));
            nm1 = fmaxf(nm1, __shfl_xor_sync(0xffffffffu, nm1, 2));
            float alpha0 = fast_exp2(m0 - nm0), alpha1 = fast_exp2(m1 - nm1);

            float ls0 = 0.f, ls1 = 0.f;
            uint32_t pa[4][4];
#pragma unroll
            for (int nt = 0; nt < 8; nt++) {
                __half2 e0 = h2exp2(__floats2half2_rn(sacc[nt][0] - nm0,
                                                      sacc[nt][1] - nm0));
                __half2 e1 = h2exp2(__floats2half2_rn(sacc[nt][2] - nm1,
                                                      sacc[nt][3] - nm1));
                float2 f0 = __half22float2(e0);
                float2 f1 = __half22float2(e1);
                ls0 += f0.x + f0.y;
                ls1 += f1.x + f1.y;
                int kt = nt >> 1, hi = nt & 1;
                pa[kt][hi * 2 + 0] = *reinterpret_cast<uint32_t*>(&e0);
                pa[kt][hi * 2 + 1] = *reinterpret_cast<uint32_t*>(&e1);
            }
            ls0 += __shfl_xor_sync(0xffffffffu, ls0, 1);
            ls0 += __shfl_xor_sync(0xffffffffu, ls0, 2);
            ls1 += __shfl_xor_sync(0xffffffffu, ls1, 1);
            ls1 += __shfl_xor_sync(0xffffffffu, ls1, 2);
            l0 = l0 * alpha0 + ls0;
            l1 = l1 * alpha1 + ls1;
            m0 = nm0;
            m1 = nm1;
#pragma unroll
            for (int dnt = 0; dnt < 8; dnt++) {
                o[dnt][0] *= alpha0; o[dnt][1] *= alpha0;
                o[dnt][2] *= alpha1; o[dnt][3] *= alpha1;
            }

            // O += P V over the 64 rows of this half
#pragma unroll
            for (int kt = 0; kt < 4; kt++) {
#pragma unroll
                for (int dp = 0; dp < 4; dp++) {
                    uint32_t r[4];
                    ldsm_x4_trans(r, vs + v_lm +
                                     (half * 4 + kt) * 16 * AT_LKB + dp * 32);
                    mma16816(o[dp * 2],     pa[kt], r);
                    mma16816(o[dp * 2 + 1], pa[kt], r + 2);
                }
            }
        }
        stage ^= 1;
    }

    float inv0 = 1.f / l0, inv1 = 1.f / l1;
    int b = bh >> 4, h = bh & 15;
    int s0 = qb * 128 + warp * 16 + g;
    size_t r0 = (size_t)(b * SEQ + s0) * DMODEL + h * HDIM;
    size_t r1 = r0 + (size_t)8 * DMODEL;
#pragma unroll
    for (int dnt = 0; dnt < 8; dnt++) {
        int d = dnt * 8 + tg * 2;
        *reinterpret_cast<uint32_t*>(&Aout[r0 + d]) =
            pack_half2f(o[dnt][0] * inv0, o[dnt][1] * inv0);
        *reinterpret_cast<uint32_t*>(&Aout[r1 + d]) =
            pack_half2f(o[dnt][2] * inv1, o[dnt][3] * inv1);
    }
}

// --------------------------- residual + layernorm --------------------------
__global__ __launch_bounds__(256) void ln_kernel(
    const float* __restrict__ X, const float* __restrict__ Y,
    const float* __restrict__ gg, const float* __restrict__ bb,
    float* __restrict__ out32, __half* __restrict__ out16) {
    const int row = blockIdx.x, tid = threadIdx.x;
    const size_t roff = (size_t)row * DMODEL;
    float4 xv = reinterpret_cast<const float4*>(X + roff)[tid];
    float4 yv = reinterpret_cast<const float4*>(Y + roff)[tid];
    float v[4] = {xv.x + yv.x, xv.y + yv.y, xv.z + yv.z, xv.w + yv.w};
    float s = v[0] + v[1] + v[2] + v[3];

    __shared__ float red[8], red2[8];
#pragma unroll
    for (int o = 16; o; o >>= 1) s += __shfl_xor_sync(0xffffffffu, s, o);
    if ((tid & 31) == 0) red[tid >> 5] = s;
    __syncthreads();
    float tot = 0.f;
#pragma unroll
    for (int i = 0; i < 8; i++) tot += red[i];
    float mean = tot * (1.0f / DMODEL);

    float s2 = 0.f;
#pragma unroll
    for (int i = 0; i < 4; i++) {
        float d = v[i] - mean;
        s2 += d * d;
    }
#pragma unroll
    for (int o = 16; o; o >>= 1) s2 += __shfl_xor_sync(0xffffffffu, s2, o);
    if ((tid & 31) == 0) red2[tid >> 5] = s2;
    __syncthreads();
    float tot2 = 0.f;
#pragma unroll
    for (int i = 0; i < 8; i++) tot2 += red2[i];
    float rstd = rsqrtf(tot2 * (1.0f / DMODEL) + 1e-5f);

    float4 gv = reinterpret_cast<const float4*>(gg)[tid];
    float4 bv = reinterpret_cast<const float4*>(bb)[tid];
    float4 nv;
    nv.x = (v[0] - mean) * rstd * gv.x + bv.x;
    nv.y = (v[1] - mean) * rstd * gv.y + bv.y;
    nv.z = (v[2] - mean) * rstd * gv.z + bv.z;
    nv.w = (v[3] - mean) * rstd * gv.w + bv.w;
    reinterpret_cast<float4*>(out32 + roff)[tid] = nv;
    if (out16) {
        *reinterpret_cast<uint2*>(out16 + roff + tid * 4) =
            make_uint2(pack_half2f(nv.x, nv.y), pack_half2f(nv.z, nv.w));
    }
}

// ------------------------------- host --------------------------------------
extern "C" void kernel_launch(void* const* d_in, const int* in_sizes, int n_in,
                              void* d_out, int out_size) {
    const float* x       = (const float*)d_in[0];
    const float* w_attn  = (const float*)d_in[1];
    const float* b_attn  = (const float*)d_in[2];
    const float* w_aproj = (const float*)d_in[3];
    const float* b_aproj = (const float*)d_in[4];
    const float* g1      = (const float*)d_in[5];
    const float* b1      = (const float*)d_in[6];
    const float* w_fc    = (const float*)d_in[7];
    const float* b_fc    = (const float*)d_in[8];
    const float* w_mproj = (const float*)d_in[9];
    const float* b_mproj = (const float*)d_in[10];
    const float* g2      = (const float*)d_in[11];
    const float* b2      = (const float*)d_in[12];
    float* out = (float*)d_out;

    __half *x16, *wattnT, *waprojT, *wfcT, *wmprojT, *q16, *k16, *v16, *a16, *n16, *h16;
    float *ap32, *n32, *m32;
    cudaGetSymbolAddress((void**)&x16,     g_x16);
    cudaGetSymbolAddress((void**)&wattnT,  g_wattnT);
    cudaGetSymbolAddress((void**)&waprojT, g_waprojT);
    cudaGetSymbolAddress((void**)&wfcT,    g_wfcT);
    cudaGetSymbolAddress((void**)&wmprojT, g_wmprojT);
    cudaGetSymbolAddress((void**)&q16,     g_q16);
    cudaGetSymbolAddress((void**)&k16,     g_k16);
    cudaGetSymbolAddress((void**)&v16,     g_v16);
    cudaGetSymbolAddress((void**)&a16,     g_a16);
    cudaGetSymbolAddress((void**)&n16,     g_n16);
    cudaGetSymbolAddress((void**)&h16,     g_h16);
    cudaGetSymbolAddress((void**)&ap32,    g_ap32);
    cudaGetSymbolAddress((void**)&n32,     g_n32);
    cudaGetSymbolAddress((void**)&m32,     g_m32);

    cudaFuncSetAttribute(gemm_v6<EPI_QKV>,  cudaFuncAttributeMaxDynamicSharedMemorySize, G6_SMEM);
    cudaFuncSetAttribute(gemm_v6<EPI_F32>,  cudaFuncAttributeMaxDynamicSharedMemorySize, G6_SMEM);
    cudaFuncSetAttribute(gemm_v6<EPI_GELU>, cudaFuncAttributeMaxDynamicSharedMemorySize, G6_SMEM);
    cudaFuncSetAttribute(attn_kernel,       cudaFuncAttributeMaxDynamicSharedMemorySize, ASMEM);

    // launch 0: fused prep
    prep_all<<<20480, 256>>>(x, w_attn, w_aproj, w_fc, w_mproj,
                             x16, wattnT, waprojT, wfcT, wmprojT);

    // launch 1: qkv (N = 3072, K = 1024)
    gemm_v6<EPI_QKV><<<dim3(3 * DMODEL / 64, ROWS / 128), 256, G6_SMEM>>>(
        x16, wattnT, b_attn, nullptr, nullptr, q16, k16, v16, 3 * DMODEL, DMODEL);

    // launch 2: attention (1-D longest-first grid)
    attn_kernel<<<(SEQ / 128) * BATCH * NHEAD, 256, ASMEM>>>(q16, k16, v16, a16);

    // launch 3: aproj (N = K = 1024)
    gemm_v6<EPI_F32><<<dim3(DMODEL / 64, ROWS / 128), 256, G6_SMEM>>>(
        a16, waprojT, b_aproj, ap32, nullptr, nullptr, nullptr, nullptr,
        DMODEL, DMODEL);

    // launch 4: n = LN(x + aproj)
    ln_kernel<<<ROWS, 256>>>(x, ap32, g1, b1, n32, n16);

    // launch 5: fc + gelu (N = 4096, K = 1024)   <- ncu -s 5 -c 1 captures this
    gemm_v6<EPI_GELU><<<dim3(DFF / 64, ROWS / 128), 256, G6_SMEM>>>(
        n16, wfcT, b_fc, nullptr, h16, nullptr, nullptr, nullptr,
        DFF, DMODEL);

    // launch 6: mproj (N = 1024, K = 4096)
    gemm_v6<EPI_F32><<<dim3(DMODEL / 64, ROWS / 128), 256, G6_SMEM>>>(
        h16, wmprojT, b_mproj, m32, nullptr, nullptr, nullptr, nullptr,
        DMODEL, DFF);

    // launch 7: out = LN(n + m)
    ln_kernel<<<ROWS, 256>>>(n32, m32, g2, b2, out, nullptr);
}